// round 5
// baseline (speedup 1.0000x reference)
#include <cuda_runtime.h>
#include <cuda_fp16.h>
#include <cstdint>
#include <math.h>

#define NB 16
#define ND 256
#define NPIX 4096

// ---------------- global scratch (allocation-free) ----------------
__device__ float g_q [NB*ND*NPIX];
__device__ float g_k [NB*ND*NPIX];
__device__ float g_v [NB*ND*NPIX];
__device__ float g_ao[NB*ND*NPIX];
__device__ float g_scores[NB*64*64];
__device__ float g_attn  [NB*64*64];

__device__ __align__(16) __half g_xt [NB*NPIX*ND];   // x transposed [b][pix][c], fp16
__device__ __align__(16) __half g_aot[NB*NPIX*ND];   // attn out transposed, fp16
__device__ __align__(16) __half g_wp [3*ND*ND];      // qkv weights [proj][o][c]
__device__ __align__(16) __half g_wc [9*ND*ND];      // conv weights [khw][o][c]

// ---------------- helpers ----------------
__device__ __forceinline__ uint32_t smem_u32(const void* p){
    uint32_t a;
    asm("{ .reg .u64 t; cvta.to.shared.u64 t, %1; cvt.u32.u64 %0, t; }" : "=r"(a) : "l"(p));
    return a;
}
__device__ __forceinline__ void cp16(uint32_t saddr, const void* gaddr, bool v){
    asm volatile("cp.async.ca.shared.global [%0], [%1], 16, %2;"
        :: "r"(saddr), "l"(gaddr), "r"(v ? 16 : 0));
}
#define CP_COMMIT() asm volatile("cp.async.commit_group;" ::: "memory")
#define CP_WAIT1()  asm volatile("cp.async.wait_group 1;" ::: "memory")
#define CP_WAIT0()  asm volatile("cp.async.wait_group 0;" ::: "memory")

__device__ __forceinline__ void ldmat4(uint32_t* r, uint32_t addr){
    asm volatile("ldmatrix.sync.aligned.m8n8.x4.shared.b16 {%0,%1,%2,%3}, [%4];"
        : "=r"(r[0]), "=r"(r[1]), "=r"(r[2]), "=r"(r[3]) : "r"(addr));
}
__device__ __forceinline__ void mma16816(float* d, const uint32_t* a, const uint32_t* b){
    asm volatile("mma.sync.aligned.m16n8k16.row.col.f32.f16.f16.f32 "
        "{%0,%1,%2,%3}, {%4,%5,%6,%7}, {%8,%9}, {%0,%1,%2,%3};"
        : "+f"(d[0]), "+f"(d[1]), "+f"(d[2]), "+f"(d[3])
        : "r"(a[0]), "r"(a[1]), "r"(a[2]), "r"(a[3]), "r"(b[0]), "r"(b[1]));
}

// ---------------- QKV persistent-A kernel ----------------
// smem: A[256 o][256 k] fp16 swizzled (128KB) + 3 x B[128 pix][64 k] (16KB each)
#define QKV_A_BYTES   131072
#define QKV_B_BYTES   16384
#define QKV_SMEM      (QKV_A_BYTES + 3*QKV_B_BYTES)

__global__ void __launch_bounds__(512, 1) qkv_mma_kernel(
    const float* __restrict__ bq, const float* __restrict__ bk, const float* __restrict__ bv)
{
    extern __shared__ char smem[];
    const uint32_t sbase = smem_u32(smem);
    const int tid = threadIdx.x;
    const int lane = tid & 31, wid = tid >> 5;
    const int om = wid >> 2, pn = wid & 3;          // warp tile: o 64, pix 32
    const int ngroup = blockIdx.x;                  // 0..7, 4 pixel tiles each
    const int bp = blockIdx.y;                      // 0..47
    const int proj = bp % 3, b = bp / 3;

    const __half* A = g_wp + (size_t)proj * 65536;
    const __half* B = g_xt + (size_t)b * NPIX * ND;

    // ---- load persistent A (256x256) + B stage 0, group 0; B stage 1, group 1 ----
    {
        #pragma unroll
        for (int q = 0; q < 16; q++) {
            const int idx = tid + q * 512;          // 0..8191
            const int o = idx >> 5, c = idx & 31;
            cp16(sbase + o * 512 + ((c ^ (o & 7)) << 4), A + (size_t)o * 256 + c * 8, true);
        }
        // B stage 0 (tile 0, chunk 0)
        const int n0 = ngroup * 512;
        #pragma unroll
        for (int q = 0; q < 2; q++) {
            const int idx = tid + q * 512;          // 0..1023
            const int m = idx >> 3, c = idx & 7;
            cp16(sbase + QKV_A_BYTES + m * 128 + ((c ^ (m & 7)) << 4),
                 B + (size_t)(n0 + m) * 256 + c * 8, true);
        }
        CP_COMMIT();
        // B stage 1 (tile 0, chunk 1)
        #pragma unroll
        for (int q = 0; q < 2; q++) {
            const int idx = tid + q * 512;
            const int m = idx >> 3, c = idx & 7;
            cp16(sbase + QKV_A_BYTES + QKV_B_BYTES + m * 128 + ((c ^ (m & 7)) << 4),
                 B + (size_t)(n0 + m) * 256 + 64 + c * 8, true);
        }
        CP_COMMIT();
    }

    float acc[4][4][4];
    #pragma unroll
    for (int i = 0; i < 4; i++)
        #pragma unroll
        for (int j = 0; j < 4; j++)
            #pragma unroll
            for (int q = 0; q < 4; q++) acc[i][j][q] = 0.f;

    const float* bias = (proj == 0) ? bq : (proj == 1) ? bk : bv;
    float* dstbase = ((proj == 0) ? g_q : (proj == 1) ? g_k : g_v) + (size_t)b * ND * NPIX;

    #pragma unroll 1
    for (int s = 0; s < 16; s++) {                  // s = tile*4 + chunk
        if (s < 14) { CP_WAIT1(); } else { CP_WAIT0(); }
        __syncthreads();
        // prefetch stage s+2
        if (s + 2 < 16) {
            const int t2 = s + 2;
            const int tile2 = t2 >> 2, ch2 = t2 & 3;
            const int n2 = (ngroup * 4 + tile2) * 128;
            const uint32_t stb = sbase + QKV_A_BYTES + (t2 % 3) * QKV_B_BYTES;
            #pragma unroll
            for (int q = 0; q < 2; q++) {
                const int idx = tid + q * 512;
                const int m = idx >> 3, c = idx & 7;
                cp16(stb + m * 128 + ((c ^ (m & 7)) << 4),
                     B + (size_t)(n2 + m) * 256 + ch2 * 64 + c * 8, true);
            }
            CP_COMMIT();
        }
        // compute: chunk = s&3, B buf = s%3
        {
            const int chunk = s & 3;
            const uint32_t bbuf = sbase + QKV_A_BYTES + (s % 3) * QKV_B_BYTES;
            #pragma unroll
            for (int kh = 0; kh < 4; kh++) {
                uint32_t ah[4][4], bf[4][2];
                const int c32 = (chunk * 4 + kh) * 2 + (lane >> 4);
                #pragma unroll
                for (int i = 0; i < 4; i++) {
                    const int row = om * 64 + i * 16 + (lane & 15);
                    ldmat4(ah[i], sbase + row * 512 + ((c32 ^ (row & 7)) << 4));
                }
                #pragma unroll
                for (int jj = 0; jj < 2; jj++) {
                    const int row = pn * 32 + jj * 16 + (lane & 7) + ((lane >> 4) << 3);
                    const int ch = (2 * kh + ((lane >> 3) & 1)) ^ (row & 7);
                    uint32_t r4[4];
                    ldmat4(r4, bbuf + row * 128 + ch * 16);
                    bf[2*jj][0] = r4[0]; bf[2*jj][1] = r4[1];
                    bf[2*jj+1][0] = r4[2]; bf[2*jj+1][1] = r4[3];
                }
                #pragma unroll
                for (int i = 0; i < 4; i++)
                    #pragma unroll
                    for (int j = 0; j < 4; j++)
                        mma16816(acc[i][j], ah[i], bf[j]);
            }
        }
        // epilogue per tile
        if ((s & 3) == 3) {
            const int n0 = (ngroup * 4 + (s >> 2)) * 128;
            #pragma unroll
            for (int i = 0; i < 4; i++) {
                const int r0 = om * 64 + i * 16 + (lane >> 2);
                const float bb0 = bias[r0], bb1 = bias[r0 + 8];
                #pragma unroll
                for (int j = 0; j < 4; j++) {
                    const int cb = n0 + pn * 32 + j * 8 + 2 * (lane & 3);
                    float2 v0 = make_float2(acc[i][j][0] + bb0, acc[i][j][1] + bb0);
                    float2 v1 = make_float2(acc[i][j][2] + bb1, acc[i][j][3] + bb1);
                    *(float2*)(dstbase + (size_t)r0 * NPIX + cb) = v0;
                    *(float2*)(dstbase + (size_t)(r0 + 8) * NPIX + cb) = v1;
                    #pragma unroll
                    for (int q = 0; q < 4; q++) acc[i][j][q] = 0.f;
                }
            }
        }
    }
}

// ---------------- conv 3x3: o=256, pix=128, halo-B, BN + LeakyReLU ----------------
// smem: 3 x A[256 o][64 k] (32KB each) + 2 x Bhalo[4 row][66 col][64 k] (33792B each)
#define CV_A_BYTES   32768
#define CV_B_OFF     (3*CV_A_BYTES)
#define CV_B_BYTES   33792
#define CV_SMEM      (CV_B_OFF + 2*CV_B_BYTES)

__global__ void __launch_bounds__(512, 1) conv_mma_kernel(
    const float* __restrict__ b_out, const float* __restrict__ gamma,
    const float* __restrict__ beta,  const float* __restrict__ bn_mean,
    const float* __restrict__ bn_var, float* __restrict__ out)
{
    extern __shared__ char smem[];
    const uint32_t sbase = smem_u32(smem);
    const int tid = threadIdx.x;
    const int lane = tid & 31, wid = tid >> 5;
    const int om = wid >> 2, pn = wid & 3;          // warp tile: o 64, pix 32
    const int pt = blockIdx.x;                      // pixel tile (2 rows): h0 = pt*2
    const int b  = blockIdx.y;
    const int h0 = pt * 2;
    const int n0 = pt * 128;

    const __half* B = g_aot + (size_t)b * NPIX * ND;

    // A stage load: stage s -> khw = s%9, chunk = s/9, buffer s%3
    auto load_A = [&](int s) {
        const int khw = s % 9, chunk = s / 9;
        const uint32_t stb = sbase + (s % 3) * CV_A_BYTES;
        const __half* src = g_wc + (size_t)khw * 65536 + chunk * 64;
        #pragma unroll
        for (int q = 0; q < 4; q++) {
            const int idx = tid + q * 512;          // 0..2047
            const int o = idx >> 3, c = idx & 7;
            cp16(stb + o * 128 + ((c ^ (o & 7)) << 4), src + (size_t)o * 256 + c * 8, true);
        }
    };
    // B halo load for k-chunk: 4 rows (h0-1..h0+2) x 66 cols (w -1..64), buffer chunk&1
    auto load_B = [&](int chunk) {
        const uint32_t stb = sbase + CV_B_OFF + (chunk & 1) * CV_B_BYTES;
        for (int idx = tid; idx < 2112; idx += 512) {
            const int e = idx >> 3, c = idx & 7;    // e = hr*66 + cs
            const int hr = e / 66, cs = e - hr * 66;
            const int h = h0 - 1 + hr, w = cs - 1;
            const bool v = ((unsigned)h < 64u) && ((unsigned)w < 64u);
            const size_t boff = v ? ((size_t)(h * 64 + w) * 256 + chunk * 64 + c * 8) : 0;
            cp16(stb + e * 128 + ((c ^ (e & 7)) << 4), B + boff, v);
        }
    };

    // prologue: group0 = A(0)+B(0), group1 = A(1)
    load_A(0); load_B(0); CP_COMMIT();
    load_A(1); CP_COMMIT();

    float acc[4][4][4];
    #pragma unroll
    for (int i = 0; i < 4; i++)
        #pragma unroll
        for (int j = 0; j < 4; j++)
            #pragma unroll
            for (int q = 0; q < 4; q++) acc[i][j][q] = 0.f;

    #pragma unroll 1
    for (int s = 0; s < 36; s++) {
        if (s < 34) { CP_WAIT1(); } else { CP_WAIT0(); }
        __syncthreads();
        if (s + 2 < 36) {
            load_A(s + 2);
            if ((s + 2) % 9 == 0) load_B((s + 2) / 9);
            CP_COMMIT();
        }
        // compute stage s: khw = s%9, chunk = s/9
        {
            const int khw = s % 9, chunk = s / 9;
            const int dh = khw / 3 - 1, dw = khw % 3 - 1;
            const uint32_t abuf = sbase + (s % 3) * CV_A_BYTES;
            const uint32_t bbuf = sbase + CV_B_OFF + (chunk & 1) * CV_B_BYTES;
            #pragma unroll
            for (int kh = 0; kh < 4; kh++) {
                uint32_t ah[4][4], bf[4][2];
                #pragma unroll
                for (int i = 0; i < 4; i++) {
                    const int row = om * 64 + i * 16 + (lane & 15);
                    const int ch = (2 * kh + (lane >> 4)) ^ (row & 7);
                    ldmat4(ah[i], abuf + row * 128 + ch * 16);
                }
                #pragma unroll
                for (int jj = 0; jj < 2; jj++) {
                    const int p = pn * 32 + jj * 16 + (lane & 7) + ((lane >> 4) << 3);
                    const int e = ((p >> 6) + dh + 1) * 66 + (p & 63) + dw + 1;
                    const int ch = (2 * kh + ((lane >> 3) & 1)) ^ (e & 7);
                    uint32_t r4[4];
                    ldmat4(r4, bbuf + e * 128 + ch * 16);
                    bf[2*jj][0] = r4[0]; bf[2*jj][1] = r4[1];
                    bf[2*jj+1][0] = r4[2]; bf[2*jj+1][1] = r4[3];
                }
                #pragma unroll
                for (int i = 0; i < 4; i++)
                    #pragma unroll
                    for (int j = 0; j < 4; j++)
                        mma16816(acc[i][j], ah[i], bf[j]);
            }
        }
    }

    float* dst = out + (size_t)b * ND * NPIX;
    #pragma unroll
    for (int i = 0; i < 4; i++) {
        const int r0 = om * 64 + i * 16 + (lane >> 2);
        const float sc0 = gamma[r0]     * rsqrtf(bn_var[r0]     + 1e-5f);
        const float sc1 = gamma[r0 + 8] * rsqrtf(bn_var[r0 + 8] + 1e-5f);
        const float ad0 = (b_out[r0]     - bn_mean[r0])     * sc0 + beta[r0];
        const float ad1 = (b_out[r0 + 8] - bn_mean[r0 + 8]) * sc1 + beta[r0 + 8];
        #pragma unroll
        for (int j = 0; j < 4; j++) {
            const int cb = n0 + pn * 32 + j * 8 + 2 * (lane & 3);
            float t0 = acc[i][j][0] * sc0 + ad0;
            float t1 = acc[i][j][1] * sc0 + ad0;
            float t2 = acc[i][j][2] * sc1 + ad1;
            float t3 = acc[i][j][3] * sc1 + ad1;
            float2 v0 = make_float2((t0 >= 0.f) ? t0 : 0.2f * t0,
                                    (t1 >= 0.f) ? t1 : 0.2f * t1);
            float2 v1 = make_float2((t2 >= 0.f) ? t2 : 0.2f * t2,
                                    (t3 >= 0.f) ? t3 : 0.2f * t3);
            *(float2*)(dst + (size_t)r0 * NPIX + cb) = v0;
            *(float2*)(dst + (size_t)(r0 + 8) * NPIX + cb) = v1;
        }
    }
}

// ---------------- convert / transpose kernels ----------------
template<int SRC>
__global__ void __launch_bounds__(256) convert_transpose_kernel(const float* __restrict__ xsrc)
{
    const float* src = (SRC == 0) ? xsrc : g_ao;
    __half* dh = (SRC == 0) ? g_xt : g_aot;
    const int b = blockIdx.z, c0 = blockIdx.y * 32, p0 = blockIdx.x * 32;
    __shared__ float tile[32][33];
    const int tx = threadIdx.x & 31, ty = threadIdx.x >> 5;
    const float* s = src + ((size_t)b * ND + c0) * NPIX + p0;
    #pragma unroll
    for (int i = 0; i < 32; i += 8)
        tile[ty + i][tx] = s[(size_t)(ty + i) * NPIX + tx];
    __syncthreads();
    #pragma unroll
    for (int i = 0; i < 32; i += 8) {
        size_t di = ((size_t)b * NPIX + p0 + ty + i) * ND + c0 + tx;
        dh[di] = __float2half_rn(tile[tx][ty + i]);
    }
}

__global__ void __launch_bounds__(256) convert_wqkv_kernel(
    const float* __restrict__ wq, const float* __restrict__ wk, const float* __restrict__ wv)
{
    int i = blockIdx.x * 256 + threadIdx.x;
    const float* w = (i < 65536) ? wq : (i < 131072) ? wk : wv;
    g_wp[i] = __float2half_rn(w[i & 65535]);
}

__global__ void __launch_bounds__(256) convert_wconv_kernel(const float* __restrict__ w_out)
{
    int i = blockIdx.x * 256 + threadIdx.x;
    float v = w_out[i];
    int o = i / 2304; int rem = i - o * 2304; int c = rem / 9; int khw = rem - c * 9;
    g_wc[(size_t)khw * 65536 + (size_t)o * 256 + c] = __float2half_rn(v);
}

// ---------------- attention middle (SIMT, unchanged) ----------------
__global__ void __launch_bounds__(256) scores_partial_kernel()
{
    const int d = blockIdx.x;
    const int b = blockIdx.y;
    const int tid = threadIdx.x;
    __shared__ float Qs[64][65];
    __shared__ float Ks[64][65];
    const float* qb = g_q + ((size_t)b * ND + d) * NPIX;
    const float* kb = g_k + ((size_t)b * ND + d) * NPIX;

    for (int idx = tid; idx < 4096; idx += 256) {
        const int t = idx >> 6, l = idx & 63;
        const int off = ((t >> 3) * 8 + (l >> 3)) * 64 + (t & 7) * 8 + (l & 7);
        Qs[l][t] = qb[off];
        Ks[l][t] = kb[off];
    }
    __syncthreads();

    const int ty = tid >> 4, tx = tid & 15;
    float acc[4][4];
    #pragma unroll
    for (int i = 0; i < 4; i++)
        #pragma unroll
        for (int j = 0; j < 4; j++) acc[i][j] = 0.f;

    #pragma unroll 4
    for (int l = 0; l < 64; l++) {
        float qv[4], kv[4];
        #pragma unroll
        for (int i = 0; i < 4; i++) { qv[i] = Qs[l][ty + 16*i]; kv[i] = Ks[l][tx + 16*i]; }
        #pragma unroll
        for (int i = 0; i < 4; i++)
            #pragma unroll
            for (int j = 0; j < 4; j++) acc[i][j] += qv[i] * kv[j];
    }

    float* part = g_ao + ((size_t)b * ND + d) * NPIX;
    #pragma unroll
    for (int i = 0; i < 4; i++)
        #pragma unroll
        for (int j = 0; j < 4; j++)
            part[(ty + 16*i) * 64 + tx + 16*j] = acc[i][j];
}

__global__ void __launch_bounds__(256) scores_reduce_kernel()
{
    const int b  = blockIdx.y;
    const int tu = blockIdx.x * 256 + threadIdx.x;
    const float* pp = g_ao + (size_t)b * ND * NPIX + tu;
    float s = 0.f;
    #pragma unroll 8
    for (int d = 0; d < ND; d++) s += pp[(size_t)d * NPIX];
    g_scores[b * 4096 + tu] = s;
}

__global__ void __launch_bounds__(64) softmax_kernel()
{
    const int b = blockIdx.x;
    const int t = threadIdx.x;
    const float scale = 1.0f / 128.0f;
    const float* row = g_scores + b * 4096 + t * 64;
    float v[64];
    float m = -1e30f;
    #pragma unroll
    for (int u = 0; u < 64; u++) { v[u] = row[u] * scale; m = fmaxf(m, v[u]); }
    float s = 0.f;
    #pragma unroll
    for (int u = 0; u < 64; u++) { v[u] = __expf(v[u] - m); s += v[u]; }
    const float inv = 1.0f / s;
    float* arow = g_attn + b * 4096 + t * 64;
    #pragma unroll
    for (int u = 0; u < 64; u++) arow[u] = v[u] * inv;
}

__global__ void __launch_bounds__(256) av_kernel()
{
    const int h  = blockIdx.x;
    const int d0 = blockIdx.y * 16;
    const int b  = blockIdx.z;
    const int tid = threadIdx.x;

    __shared__ float attn_s[8][64];
    __shared__ float Vs[16][8][64];

    for (int idx = tid; idx < 512; idx += 256) {
        const int r = idx >> 6, j = idx & 63;
        attn_s[r][j] = g_attn[b * 4096 + ((h >> 3) * 8 + r) * 64 + j];
    }
    for (int idx = tid; idx < 8192; idx += 256) {
        const int dl = idx >> 9, j2 = (idx >> 6) & 7, w = idx & 63;
        Vs[dl][j2][w] = g_v[(((size_t)b * ND + d0 + dl) * 64 + j2 * 8 + (h & 7)) * 64 + w];
    }
    __syncthreads();

    const int dg = (tid >> 6) * 4;
    const int w  = tid & 63;
    float acc[4] = {0.f, 0.f, 0.f, 0.f};
    #pragma unroll 8
    for (int j = 0; j < 64; j++) {
        const float a = attn_s[w >> 3][j];
        const int col = ((j & 7) << 3) | (w & 7);
        #pragma unroll
        for (int q = 0; q < 4; q++) acc[q] += a * Vs[dg + q][j >> 3][col];
    }
    #pragma unroll
    for (int q = 0; q < 4; q++)
        g_ao[(((size_t)b * ND + d0 + dg + q) * 64 + h) * 64 + w] = acc[q];
}

// ---------------- host ----------------
extern "C" void kernel_launch(void* const* d_in, const int* in_sizes, int n_in,
                              void* d_out, int out_size)
{
    const float* x       = (const float*)d_in[0];
    const float* wq      = (const float*)d_in[1];
    const float* bq      = (const float*)d_in[2];
    const float* wk      = (const float*)d_in[3];
    const float* bk      = (const float*)d_in[4];
    const float* wv      = (const float*)d_in[5];
    const float* bv      = (const float*)d_in[6];
    const float* w_out   = (const float*)d_in[7];
    const float* b_out   = (const float*)d_in[8];
    const float* gamma   = (const float*)d_in[9];
    const float* beta    = (const float*)d_in[10];
    const float* bn_mean = (const float*)d_in[11];
    const float* bn_var  = (const float*)d_in[12];
    float* out = (float*)d_out;

    cudaFuncSetAttribute(qkv_mma_kernel,  cudaFuncAttributeMaxDynamicSharedMemorySize, QKV_SMEM);
    cudaFuncSetAttribute(conv_mma_kernel, cudaFuncAttributeMaxDynamicSharedMemorySize, CV_SMEM);

    convert_wqkv_kernel <<<768,  256>>>(wq, wk, wv);
    convert_wconv_kernel<<<2304, 256>>>(w_out);
    convert_transpose_kernel<0><<<dim3(128, 8, 16), 256>>>(x);

    qkv_mma_kernel<<<dim3(8, 48), 512, QKV_SMEM>>>(bq, bk, bv);

    scores_partial_kernel<<<dim3(256, 16), 256>>>();
    scores_reduce_kernel <<<dim3(16, 16), 256>>>();
    softmax_kernel<<<16, 64>>>();
    av_kernel<<<dim3(64, 16, 16), 256>>>();

    convert_transpose_kernel<1><<<dim3(128, 8, 16), 256>>>(nullptr);
    conv_mma_kernel<<<dim3(32, 16), 512, CV_SMEM>>>(b_out, gamma, beta, bn_mean, bn_var, out);
}

// round 6
// speedup vs baseline: 1.1530x; 1.1530x over previous
#include <cuda_runtime.h>
#include <cuda_fp16.h>
#include <cstdint>
#include <math.h>

#define NB 16
#define ND 256
#define NPIX 4096

// ---------------- global scratch (allocation-free) ----------------
__device__ float g_q [NB*ND*NPIX];
__device__ float g_k [NB*ND*NPIX];
__device__ float g_v [NB*ND*NPIX];
__device__ float g_ao[NB*ND*NPIX];
__device__ float g_scores[NB*64*64];
__device__ float g_attn  [NB*64*64];

// pre-swizzled, chunked fp16 layouts (ready for 1D bulk copy into smem)
__device__ __align__(16) __half g_xt2 [NB*4*NPIX*64];   // [b][chunk][pix][64c] swizzled
__device__ __align__(16) __half g_aot2[NB*4*NPIX*64];
__device__ __align__(16) __half g_wp2 [3*2*4*128*64];   // [proj][otile][chunk][o128][64c]
__device__ __align__(16) __half g_wc2 [9*2*4*128*64];   // [khw][otile][chunk][o128][64c]

// ---------------- helpers ----------------
__device__ __forceinline__ uint32_t smem_u32(const void* p){
    uint32_t a;
    asm("{ .reg .u64 t; cvta.to.shared.u64 t, %1; cvt.u32.u64 %0, t; }" : "=r"(a) : "l"(p));
    return a;
}
#define MB_INIT(mb, n) asm volatile("mbarrier.init.shared.b64 [%0], %1;" :: "r"(mb), "r"(n) : "memory")
#define MB_EXPECT(mb, bytes) asm volatile("mbarrier.arrive.expect_tx.shared.b64 _, [%0], %1;" :: "r"(mb), "r"(bytes) : "memory")

__device__ __forceinline__ void bulk_g2s(uint32_t dst, const void* src, uint32_t bytes, uint32_t mbar){
    asm volatile("{ .reg .u64 g; cvta.to.global.u64 g, %1;\n\t"
        "cp.async.bulk.shared::cluster.global.mbarrier::complete_tx::bytes [%0], [g], %2, [%3]; }"
        :: "r"(dst), "l"(src), "r"(bytes), "r"(mbar) : "memory");
}

#define MB_WAIT(mb, ph) do { \
    uint32_t _m = (mb); uint32_t _p = (uint32_t)(ph); uint32_t _d; \
    asm volatile("{\n\t.reg .pred p;\n\t" \
        "mbarrier.try_wait.parity.acquire.cta.shared::cta.b64 p, [%1], %2;\n\t" \
        "selp.b32 %0, 1, 0, p;\n\t}" : "=r"(_d) : "r"(_m), "r"(_p) : "memory"); \
    if (!_d) { \
        asm volatile("{\n\t.reg .pred P1;\n\t" \
            "WAIT_LOOP_%=:\n\t" \
            "mbarrier.try_wait.parity.acquire.cta.shared::cta.b64 P1, [%0], %1, 0x989680;\n\t" \
            "@P1 bra.uni WAIT_DONE_%=;\n\t" \
            "bra.uni WAIT_LOOP_%=;\n\t" \
            "WAIT_DONE_%=:\n\t}" :: "r"(_m), "r"(_p) : "memory"); \
    } \
} while(0)

__device__ __forceinline__ void ldmat4(uint32_t* r, uint32_t addr){
    asm volatile("ldmatrix.sync.aligned.m8n8.x4.shared.b16 {%0,%1,%2,%3}, [%4];"
        : "=r"(r[0]), "=r"(r[1]), "=r"(r[2]), "=r"(r[3]) : "r"(addr));
}
__device__ __forceinline__ void mma16816(float* d, const uint32_t* a, const uint32_t* b){
    asm volatile("mma.sync.aligned.m16n8k16.row.col.f32.f16.f16.f32 "
        "{%0,%1,%2,%3}, {%4,%5,%6,%7}, {%8,%9}, {%0,%1,%2,%3};"
        : "+f"(d[0]), "+f"(d[1]), "+f"(d[2]), "+f"(d[3])
        : "r"(a[0]), "r"(a[1]), "r"(a[2]), "r"(a[3]), "r"(b[0]), "r"(b[1]));
}

// ---------------- converters (write pre-swizzled layouts) ----------------
template<int SRC>
__global__ void __launch_bounds__(256) convert_transpose_kernel(const float* __restrict__ xsrc)
{
    const float* src = (SRC == 0) ? xsrc : g_ao;
    __half* dh = (SRC == 0) ? g_xt2 : g_aot2;
    const int b = blockIdx.z, c0 = blockIdx.y * 32, p0 = blockIdx.x * 32;
    __shared__ float tile[32][33];
    const int tx = threadIdx.x & 31, ty = threadIdx.x >> 5;
    const float* s = src + ((size_t)b * ND + c0) * NPIX + p0;
    #pragma unroll
    for (int i = 0; i < 32; i += 8)
        tile[ty + i][tx] = s[(size_t)(ty + i) * NPIX + tx];
    __syncthreads();
    #pragma unroll
    for (int i = 0; i < 32; i += 8) {
        const int pix = p0 + ty + i;
        const int c = c0 + tx;
        const int chunk = c >> 6, cl = c & 63;
        size_t di = ((size_t)(b * 4 + chunk) * NPIX + pix) * 64
                  + (((cl >> 3) ^ (pix & 7)) << 3) + (cl & 7);
        dh[di] = __float2half_rn(tile[tx][ty + i]);
    }
}

__global__ void __launch_bounds__(256) convert_wqkv_kernel(
    const float* __restrict__ wq, const float* __restrict__ wk, const float* __restrict__ wv)
{
    int i = blockIdx.x * 256 + threadIdx.x;          // 196608
    const float* w = (i < 65536) ? wq : (i < 131072) ? wk : wv;
    const float v = w[i & 65535];
    const int proj = i >> 16, r = i & 65535;
    const int o_g = r >> 8, c_g = r & 255;
    const int otile = o_g >> 7, o = o_g & 127, chunk = c_g >> 6, c = c_g & 63;
    const size_t pos = (size_t)(((proj * 2 + otile) * 4 + chunk)) * 8192
                     + (o << 6) + (((c >> 3) ^ (o & 7)) << 3) + (c & 7);
    g_wp2[pos] = __float2half_rn(v);
}

__global__ void __launch_bounds__(256) convert_wconv_kernel(const float* __restrict__ w_out)
{
    int i = blockIdx.x * 256 + threadIdx.x;          // 589824
    const float v = w_out[i];
    const int o_g = i / 2304;
    const int rem = i - o_g * 2304;
    const int c_g = rem / 9, khw = rem - (rem / 9) * 9;
    const int otile = o_g >> 7, o = o_g & 127, chunk = c_g >> 6, c = c_g & 63;
    const size_t pos = (size_t)(((khw * 2 + otile) * 4 + chunk)) * 8192
                     + (o << 6) + (((c >> 3) ^ (o & 7)) << 3) + (c & 7);
    g_wc2[pos] = __float2half_rn(v);
}

// ---------------- QKV GEMM: bulk-copy pipeline, 128x128 tile ----------------
// smem: [0..24) 3 mbarriers; data at +1024: 3 slots x (A 16KB + B 16KB)
#define QKV_SLOT  32768
#define QKV_SMEM  (1024 + 3*QKV_SLOT)

__global__ void __launch_bounds__(256, 2) qkv_mma_kernel(
    const float* __restrict__ bq, const float* __restrict__ bk, const float* __restrict__ bv)
{
    extern __shared__ char smem[];
    const uint32_t sb = smem_u32(smem);
    const uint32_t data = sb + 1024;
    const int tid = threadIdx.x;
    const int lane = tid & 31, wid = tid >> 5;
    const int wm = wid >> 2, wn = wid & 3;
    const int n0 = blockIdx.x * 128;
    const int otile = blockIdx.y, o0 = otile * 128;
    const int bp = blockIdx.z, proj = bp % 3, b = bp / 3;

    const __half* Asrc = g_wp2 + (size_t)((proj * 2 + otile) * 4) * 8192;
    const __half* Bsrc = g_xt2 + ((size_t)(b * 4) * NPIX + n0) * 64;

    if (tid == 0) { MB_INIT(sb, 1); MB_INIT(sb + 8, 1); MB_INIT(sb + 16, 1); }
    __syncthreads();

    auto issue = [&](int s) {
        const uint32_t mb = sb + (s % 3) * 8;
        const uint32_t dst = data + (s % 3) * QKV_SLOT;
        MB_EXPECT(mb, 32768u);
        bulk_g2s(dst,         Asrc + (size_t)s * 8192,        16384u, mb);
        bulk_g2s(dst + 16384, Bsrc + (size_t)s * NPIX * 64,   16384u, mb);
    };
    if (tid == 0) { issue(0); issue(1); issue(2); }

    float acc[4][4][4];
    #pragma unroll
    for (int i = 0; i < 4; i++)
        #pragma unroll
        for (int j = 0; j < 4; j++)
            #pragma unroll
            for (int q = 0; q < 4; q++) acc[i][j][q] = 0.f;

    #pragma unroll 1
    for (int s = 0; s < 4; s++) {
        MB_WAIT(sb + (s % 3) * 8, (s / 3) & 1);
        const uint32_t ab = data + (s % 3) * QKV_SLOT;
        const uint32_t bb = ab + 16384;
        #pragma unroll
        for (int kh = 0; kh < 4; kh++) {
            uint32_t ah[4][4], bf[4][2];
            #pragma unroll
            for (int i = 0; i < 4; i++) {
                const int row = wm * 64 + i * 16 + (lane & 15);
                const int ch = (2 * kh + (lane >> 4)) ^ (row & 7);
                ldmat4(ah[i], ab + row * 128 + ch * 16);
            }
            #pragma unroll
            for (int jj = 0; jj < 2; jj++) {
                const int row = wn * 32 + jj * 16 + (lane & 7) + ((lane >> 4) << 3);
                const int ch = (2 * kh + ((lane >> 3) & 1)) ^ (row & 7);
                uint32_t r4[4];
                ldmat4(r4, bb + row * 128 + ch * 16);
                bf[2*jj][0] = r4[0]; bf[2*jj][1] = r4[1];
                bf[2*jj+1][0] = r4[2]; bf[2*jj+1][1] = r4[3];
            }
            #pragma unroll
            for (int i = 0; i < 4; i++)
                #pragma unroll
                for (int j = 0; j < 4; j++)
                    mma16816(acc[i][j], ah[i], bf[j]);
        }
        __syncthreads();
        if (tid == 0 && s + 3 < 4) issue(s + 3);
    }

    const float* bias = (proj == 0) ? bq : (proj == 1) ? bk : bv;
    float* dst = ((proj == 0) ? g_q : (proj == 1) ? g_k : g_v) + (size_t)b * ND * NPIX;
    #pragma unroll
    for (int i = 0; i < 4; i++) {
        const int r0 = o0 + wm * 64 + i * 16 + (lane >> 2);
        const float bb0 = bias[r0], bb1 = bias[r0 + 8];
        #pragma unroll
        for (int j = 0; j < 4; j++) {
            const int cb = n0 + wn * 32 + j * 8 + 2 * (lane & 3);
            float2 v0 = make_float2(acc[i][j][0] + bb0, acc[i][j][1] + bb0);
            float2 v1 = make_float2(acc[i][j][2] + bb1, acc[i][j][3] + bb1);
            *(float2*)(dst + (size_t)r0 * NPIX + cb) = v0;
            *(float2*)(dst + (size_t)(r0 + 8) * NPIX + cb) = v1;
        }
    }
}

// ---------------- conv 3x3: bulk pipeline + halo reuse + BN + LeakyReLU ----------------
// smem: [0..32) 4 mbarriers (3 A + 1 halo); data at +1024:
//   A slots 3 x 16KB (49152), halo 4 rows x 66 cols x 128B = 33792
#define CV_A_SLOT  16384
#define CV_HALO    (1024 + 3*CV_A_SLOT)
#define CV_SMEM    (CV_HALO + 33792)

__global__ void __launch_bounds__(256, 2) conv_mma_kernel(
    const float* __restrict__ b_out, const float* __restrict__ gamma,
    const float* __restrict__ beta,  const float* __restrict__ bn_mean,
    const float* __restrict__ bn_var, float* __restrict__ out)
{
    extern __shared__ char smem[];
    const uint32_t sb = smem_u32(smem);
    const uint32_t data = sb + 1024;
    const uint32_t halo = sb + CV_HALO;
    const int tid = threadIdx.x;
    const int lane = tid & 31, wid = tid >> 5;
    const int wm = wid >> 2, wn = wid & 3;
    const int pt = blockIdx.x;                 // 0..31  (h0 = pt*2, pixel tile 128)
    const int otile = blockIdx.y, o0 = otile * 128;
    const int b = blockIdx.z;
    const int h0 = pt * 2, n0 = pt * 128;

    const __half* Bbase = g_aot2 + (size_t)(b * 4) * NPIX * 64;

    if (tid == 0) { MB_INIT(sb, 1); MB_INIT(sb + 8, 1); MB_INIT(sb + 16, 1); MB_INIT(sb + 24, 1); }
    // zero-fill halo once (padding cols/rows persist across chunks)
    {
        const int4 z = make_int4(0, 0, 0, 0);
        for (int idx = tid; idx < 2112; idx += 256)
            *(int4*)(smem + CV_HALO + idx * 16) = z;
    }
    __syncthreads();

    auto issueA = [&](int s) {          // s = chunk*9 + khw
        const int khw = s % 9, chunk = s / 9;
        const uint32_t mb = sb + (s % 3) * 8;
        MB_EXPECT(mb, 16384u);
        bulk_g2s(data + (s % 3) * CV_A_SLOT,
                 g_wc2 + (size_t)((khw * 2 + otile) * 4 + chunk) * 8192, 16384u, mb);
    };
    auto issueHalo = [&](int chunk) {
        const uint32_t mb = sb + 24;
        uint32_t bytes = 0;
        #pragma unroll
        for (int hr = 0; hr < 4; hr++) {
            const int h2 = h0 - 1 + hr;
            if ((unsigned)h2 < 64u) bytes += 8192u;
        }
        MB_EXPECT(mb, bytes);
        #pragma unroll
        for (int hr = 0; hr < 4; hr++) {
            const int h2 = h0 - 1 + hr;
            if ((unsigned)h2 < 64u)
                bulk_g2s(halo + hr * 8448 + 128,
                         Bbase + ((size_t)chunk * NPIX + h2 * 64) * 64, 8192u, mb);
        }
    };
    if (tid == 0) { issueHalo(0); issueA(0); issueA(1); issueA(2); }

    float acc[4][4][4];
    #pragma unroll
    for (int i = 0; i < 4; i++)
        #pragma unroll
        for (int j = 0; j < 4; j++)
            #pragma unroll
            for (int q = 0; q < 4; q++) acc[i][j][q] = 0.f;

    #pragma unroll 1
    for (int s = 0; s < 36; s++) {
        const int khw = s % 9, chunk = s / 9;
        MB_WAIT(sb + (s % 3) * 8, (s / 3) & 1);
        if (khw == 0) MB_WAIT(sb + 24, chunk & 1);
        const int dh = khw / 3 - 1, dw = khw % 3 - 1;
        const uint32_t ab = data + (s % 3) * CV_A_SLOT;
        #pragma unroll
        for (int kh = 0; kh < 4; kh++) {
            uint32_t ah[4][4], bf[4][2];
            #pragma unroll
            for (int i = 0; i < 4; i++) {
                const int row = wm * 64 + i * 16 + (lane & 15);
                const int ch = (2 * kh + (lane >> 4)) ^ (row & 7);
                ldmat4(ah[i], ab + row * 128 + ch * 16);
            }
            #pragma unroll
            for (int jj = 0; jj < 2; jj++) {
                const int p = wn * 32 + jj * 16 + (lane & 7) + ((lane >> 4) << 3);
                const int w2 = (p & 63) + dw;                 // -1..64
                const int er = (p >> 6) + dh + 1;             // 0..3
                const int e = er * 66 + w2 + 1;
                const int ch = (2 * kh + ((lane >> 3) & 1)) ^ (w2 & 7);
                uint32_t r4[4];
                ldmat4(r4, halo + e * 128 + ch * 16);
                bf[2*jj][0] = r4[0]; bf[2*jj][1] = r4[1];
                bf[2*jj+1][0] = r4[2]; bf[2*jj+1][1] = r4[3];
            }
            #pragma unroll
            for (int i = 0; i < 4; i++)
                #pragma unroll
                for (int j = 0; j < 4; j++)
                    mma16816(acc[i][j], ah[i], bf[j]);
        }
        __syncthreads();
        if (tid == 0) {
            if (s + 3 < 36) issueA(s + 3);
            if (khw == 8 && chunk < 3) issueHalo(chunk + 1);
        }
    }

    float* dst = out + (size_t)b * ND * NPIX;
    #pragma unroll
    for (int i = 0; i < 4; i++) {
        const int r0 = o0 + wm * 64 + i * 16 + (lane >> 2);
        const float sc0 = gamma[r0]     * rsqrtf(bn_var[r0]     + 1e-5f);
        const float sc1 = gamma[r0 + 8] * rsqrtf(bn_var[r0 + 8] + 1e-5f);
        const float ad0 = (b_out[r0]     - bn_mean[r0])     * sc0 + beta[r0];
        const float ad1 = (b_out[r0 + 8] - bn_mean[r0 + 8]) * sc1 + beta[r0 + 8];
        #pragma unroll
        for (int j = 0; j < 4; j++) {
            const int cb = n0 + wn * 32 + j * 8 + 2 * (lane & 3);
            float t0 = acc[i][j][0] * sc0 + ad0;
            float t1 = acc[i][j][1] * sc0 + ad0;
            float t2 = acc[i][j][2] * sc1 + ad1;
            float t3 = acc[i][j][3] * sc1 + ad1;
            float2 v0 = make_float2((t0 >= 0.f) ? t0 : 0.2f * t0,
                                    (t1 >= 0.f) ? t1 : 0.2f * t1);
            float2 v1 = make_float2((t2 >= 0.f) ? t2 : 0.2f * t2,
                                    (t3 >= 0.f) ? t3 : 0.2f * t3);
            *(float2*)(dst + (size_t)r0 * NPIX + cb) = v0;
            *(float2*)(dst + (size_t)(r0 + 8) * NPIX + cb) = v1;
        }
    }
}

// ---------------- attention middle (SIMT, unchanged from R4) ----------------
__global__ void __launch_bounds__(256) scores_partial_kernel()
{
    const int d = blockIdx.x;
    const int b = blockIdx.y;
    const int tid = threadIdx.x;
    __shared__ float Qs[64][65];
    __shared__ float Ks[64][65];
    const float* qb = g_q + ((size_t)b * ND + d) * NPIX;
    const float* kb = g_k + ((size_t)b * ND + d) * NPIX;

    for (int idx = tid; idx < 4096; idx += 256) {
        const int t = idx >> 6, l = idx & 63;
        const int off = ((t >> 3) * 8 + (l >> 3)) * 64 + (t & 7) * 8 + (l & 7);
        Qs[l][t] = qb[off];
        Ks[l][t] = kb[off];
    }
    __syncthreads();

    const int ty = tid >> 4, tx = tid & 15;
    float acc[4][4];
    #pragma unroll
    for (int i = 0; i < 4; i++)
        #pragma unroll
        for (int j = 0; j < 4; j++) acc[i][j] = 0.f;

    #pragma unroll 4
    for (int l = 0; l < 64; l++) {
        float qv[4], kv[4];
        #pragma unroll
        for (int i = 0; i < 4; i++) { qv[i] = Qs[l][ty + 16*i]; kv[i] = Ks[l][tx + 16*i]; }
        #pragma unroll
        for (int i = 0; i < 4; i++)
            #pragma unroll
            for (int j = 0; j < 4; j++) acc[i][j] += qv[i] * kv[j];
    }

    float* part = g_ao + ((size_t)b * ND + d) * NPIX;
    #pragma unroll
    for (int i = 0; i < 4; i++)
        #pragma unroll
        for (int j = 0; j < 4; j++)
            part[(ty + 16*i) * 64 + tx + 16*j] = acc[i][j];
}

__global__ void __launch_bounds__(256) scores_reduce_kernel()
{
    const int b  = blockIdx.y;
    const int tu = blockIdx.x * 256 + threadIdx.x;
    const float* pp = g_ao + (size_t)b * ND * NPIX + tu;
    float s = 0.f;
    #pragma unroll 8
    for (int d = 0; d < ND; d++) s += pp[(size_t)d * NPIX];
    g_scores[b * 4096 + tu] = s;
}

__global__ void __launch_bounds__(64) softmax_kernel()
{
    const int b = blockIdx.x;
    const int t = threadIdx.x;
    const float scale = 1.0f / 128.0f;
    const float* row = g_scores + b * 4096 + t * 64;
    float v[64];
    float m = -1e30f;
    #pragma unroll
    for (int u = 0; u < 64; u++) { v[u] = row[u] * scale; m = fmaxf(m, v[u]); }
    float s = 0.f;
    #pragma unroll
    for (int u = 0; u < 64; u++) { v[u] = __expf(v[u] - m); s += v[u]; }
    const float inv = 1.0f / s;
    float* arow = g_attn + b * 4096 + t * 64;
    #pragma unroll
    for (int u = 0; u < 64; u++) arow[u] = v[u] * inv;
}

__global__ void __launch_bounds__(256) av_kernel()
{
    const int h  = blockIdx.x;
    const int d0 = blockIdx.y * 16;
    const int b  = blockIdx.z;
    const int tid = threadIdx.x;

    __shared__ float attn_s[8][64];
    __shared__ float Vs[16][8][64];

    for (int idx = tid; idx < 512; idx += 256) {
        const int r = idx >> 6, j = idx & 63;
        attn_s[r][j] = g_attn[b * 4096 + ((h >> 3) * 8 + r) * 64 + j];
    }
    for (int idx = tid; idx < 8192; idx += 256) {
        const int dl = idx >> 9, j2 = (idx >> 6) & 7, w = idx & 63;
        Vs[dl][j2][w] = g_v[(((size_t)b * ND + d0 + dl) * 64 + j2 * 8 + (h & 7)) * 64 + w];
    }
    __syncthreads();

    const int dg = (tid >> 6) * 4;
    const int w  = tid & 63;
    float acc[4] = {0.f, 0.f, 0.f, 0.f};
    #pragma unroll 8
    for (int j = 0; j < 64; j++) {
        const float a = attn_s[w >> 3][j];
        const int col = ((j & 7) << 3) | (w & 7);
        #pragma unroll
        for (int q = 0; q < 4; q++) acc[q] += a * Vs[dg + q][j >> 3][col];
    }
    #pragma unroll
    for (int q = 0; q < 4; q++)
        g_ao[(((size_t)b * ND + d0 + dg + q) * 64 + h) * 64 + w] = acc[q];
}

// ---------------- host ----------------
extern "C" void kernel_launch(void* const* d_in, const int* in_sizes, int n_in,
                              void* d_out, int out_size)
{
    const float* x       = (const float*)d_in[0];
    const float* wq      = (const float*)d_in[1];
    const float* bq      = (const float*)d_in[2];
    const float* wk      = (const float*)d_in[3];
    const float* bk      = (const float*)d_in[4];
    const float* wv      = (const float*)d_in[5];
    const float* bv      = (const float*)d_in[6];
    const float* w_out   = (const float*)d_in[7];
    const float* b_out   = (const float*)d_in[8];
    const float* gamma   = (const float*)d_in[9];
    const float* beta    = (const float*)d_in[10];
    const float* bn_mean = (const float*)d_in[11];
    const float* bn_var  = (const float*)d_in[12];
    float* out = (float*)d_out;

    cudaFuncSetAttribute(qkv_mma_kernel,  cudaFuncAttributeMaxDynamicSharedMemorySize, QKV_SMEM);
    cudaFuncSetAttribute(conv_mma_kernel, cudaFuncAttributeMaxDynamicSharedMemorySize, CV_SMEM);

    convert_wqkv_kernel <<<768,  256>>>(wq, wk, wv);
    convert_wconv_kernel<<<2304, 256>>>(w_out);
    convert_transpose_kernel<0><<<dim3(128, 8, 16), 256>>>(x);

    qkv_mma_kernel<<<dim3(32, 2, 48), 256, QKV_SMEM>>>(bq, bk, bv);

    scores_partial_kernel<<<dim3(256, 16), 256>>>();
    scores_reduce_kernel <<<dim3(16, 16), 256>>>();
    softmax_kernel<<<16, 64>>>();
    av_kernel<<<dim3(64, 16, 16), 256>>>();

    convert_transpose_kernel<1><<<dim3(128, 8, 16), 256>>>(nullptr);
    conv_mma_kernel<<<dim3(32, 2, 16), 256, CV_SMEM>>>(b_out, gamma, beta, bn_mean, bn_var, out);
}

// round 7
// speedup vs baseline: 1.3915x; 1.2068x over previous
#include <cuda_runtime.h>
#include <cuda_fp16.h>
#include <cstdint>
#include <math.h>

#define NB 16
#define ND 256
#define NPIX 4096

// ---------------- global scratch (allocation-free) ----------------
__device__ float g_v [NB*ND*NPIX];                       // V fp32 (for av)
__device__ float g_spart[NB*8*64*64];                    // score partials per e-slice
__device__ float g_attn [NB*64*64];

__device__ __align__(16) __half g_qt [NB*64*16384];      // Q token-major [b][t][e]
__device__ __align__(16) __half g_kt [NB*64*16384];      // K token-major [b][t][e]
__device__ __align__(16) __half g_xt2 [NB*4*NPIX*64];    // x  [b][chunk][pix][64c] swizzled
__device__ __align__(16) __half g_aot2[NB*4*NPIX*64];    // attn-out, same layout (conv input)
__device__ __align__(16) __half g_wp2 [3*2*4*128*64];    // [proj][otile][chunk][o128][64c]
__device__ __align__(16) __half g_wc2 [9*2*4*128*64];    // [khw][otile][chunk][o128][64c]

// ---------------- helpers ----------------
__device__ __forceinline__ uint32_t smem_u32(const void* p){
    uint32_t a;
    asm("{ .reg .u64 t; cvta.to.shared.u64 t, %1; cvt.u32.u64 %0, t; }" : "=r"(a) : "l"(p));
    return a;
}
#define MB_INIT(mb, n) asm volatile("mbarrier.init.shared.b64 [%0], %1;" :: "r"(mb), "r"(n) : "memory")
#define MB_EXPECT(mb, bytes) asm volatile("mbarrier.arrive.expect_tx.shared.b64 _, [%0], %1;" :: "r"(mb), "r"(bytes) : "memory")

__device__ __forceinline__ void bulk_g2s(uint32_t dst, const void* src, uint32_t bytes, uint32_t mbar){
    asm volatile("{ .reg .u64 g; cvta.to.global.u64 g, %1;\n\t"
        "cp.async.bulk.shared::cluster.global.mbarrier::complete_tx::bytes [%0], [g], %2, [%3]; }"
        :: "r"(dst), "l"(src), "r"(bytes), "r"(mbar) : "memory");
}

#define MB_WAIT(mb, ph) do { \
    uint32_t _m = (mb); uint32_t _p = (uint32_t)(ph); uint32_t _d; \
    asm volatile("{\n\t.reg .pred p;\n\t" \
        "mbarrier.try_wait.parity.acquire.cta.shared::cta.b64 p, [%1], %2;\n\t" \
        "selp.b32 %0, 1, 0, p;\n\t}" : "=r"(_d) : "r"(_m), "r"(_p) : "memory"); \
    if (!_d) { \
        asm volatile("{\n\t.reg .pred P1;\n\t" \
            "WAIT_LOOP_%=:\n\t" \
            "mbarrier.try_wait.parity.acquire.cta.shared::cta.b64 P1, [%0], %1, 0x989680;\n\t" \
            "@P1 bra.uni WAIT_DONE_%=;\n\t" \
            "bra.uni WAIT_LOOP_%=;\n\t" \
            "WAIT_DONE_%=:\n\t}" :: "r"(_m), "r"(_p) : "memory"); \
    } \
} while(0)

__device__ __forceinline__ void cp16(uint32_t saddr, const void* gaddr){
    asm volatile("cp.async.ca.shared.global [%0], [%1], 16;"
        :: "r"(saddr), "l"(gaddr));
}
#define CP_COMMIT() asm volatile("cp.async.commit_group;" ::: "memory")
#define CP_WAIT1()  asm volatile("cp.async.wait_group 1;" ::: "memory")
#define CP_WAIT0()  asm volatile("cp.async.wait_group 0;" ::: "memory")

__device__ __forceinline__ void ldmat4(uint32_t* r, uint32_t addr){
    asm volatile("ldmatrix.sync.aligned.m8n8.x4.shared.b16 {%0,%1,%2,%3}, [%4];"
        : "=r"(r[0]), "=r"(r[1]), "=r"(r[2]), "=r"(r[3]) : "r"(addr));
}
__device__ __forceinline__ void mma16816(float* d, const uint32_t* a, const uint32_t* b){
    asm volatile("mma.sync.aligned.m16n8k16.row.col.f32.f16.f16.f32 "
        "{%0,%1,%2,%3}, {%4,%5,%6,%7}, {%8,%9}, {%0,%1,%2,%3};"
        : "+f"(d[0]), "+f"(d[1]), "+f"(d[2]), "+f"(d[3])
        : "r"(a[0]), "r"(a[1]), "r"(a[2]), "r"(a[3]), "r"(b[0]), "r"(b[1]));
}

// ---------------- converters ----------------
__global__ void __launch_bounds__(256) convert_x_kernel(const float* __restrict__ xsrc)
{
    const int b = blockIdx.z, c0 = blockIdx.y * 32, p0 = blockIdx.x * 32;
    __shared__ float tile[32][33];
    const int tx = threadIdx.x & 31, ty = threadIdx.x >> 5;
    const float* s = xsrc + ((size_t)b * ND + c0) * NPIX + p0;
    #pragma unroll
    for (int i = 0; i < 32; i += 8)
        tile[ty + i][tx] = s[(size_t)(ty + i) * NPIX + tx];
    __syncthreads();
    #pragma unroll
    for (int i = 0; i < 32; i += 8) {
        const int pix = p0 + ty + i;
        const int c = c0 + tx;
        const int chunk = c >> 6, cl = c & 63;
        size_t di = ((size_t)(b * 4 + chunk) * NPIX + pix) * 64
                  + (((cl >> 3) ^ (pix & 7)) << 3) + (cl & 7);
        g_xt2[di] = __float2half_rn(tile[tx][ty + i]);
    }
}

__global__ void __launch_bounds__(256) convert_wqkv_kernel(
    const float* __restrict__ wq, const float* __restrict__ wk, const float* __restrict__ wv)
{
    int i = blockIdx.x * 256 + threadIdx.x;
    const float* w = (i < 65536) ? wq : (i < 131072) ? wk : wv;
    const float v = w[i & 65535];
    const int proj = i >> 16, r = i & 65535;
    const int o_g = r >> 8, c_g = r & 255;
    const int otile = o_g >> 7, o = o_g & 127, chunk = c_g >> 6, c = c_g & 63;
    const size_t pos = (size_t)(((proj * 2 + otile) * 4 + chunk)) * 8192
                     + (o << 6) + (((c >> 3) ^ (o & 7)) << 3) + (c & 7);
    g_wp2[pos] = __float2half_rn(v);
}

__global__ void __launch_bounds__(256) convert_wconv_kernel(const float* __restrict__ w_out)
{
    int i = blockIdx.x * 256 + threadIdx.x;
    const float v = w_out[i];
    const int o_g = i / 2304;
    const int rem = i - o_g * 2304;
    const int c_g = rem / 9, khw = rem - (rem / 9) * 9;
    const int otile = o_g >> 7, o = o_g & 127, chunk = c_g >> 6, c = c_g & 63;
    const size_t pos = (size_t)(((khw * 2 + otile) * 4 + chunk)) * 8192
                     + (o << 6) + (((c >> 3) ^ (o & 7)) << 3) + (c & 7);
    g_wc2[pos] = __float2half_rn(v);
}

// ---------------- QKV GEMM: bulk pipeline; Q/K -> fp16 token-major, V -> fp32 ----------------
#define QKV_SLOT  32768
#define QKV_SMEM  (1024 + 3*QKV_SLOT)

__global__ void __launch_bounds__(256, 2) qkv_mma_kernel(
    const float* __restrict__ bq, const float* __restrict__ bk, const float* __restrict__ bv)
{
    extern __shared__ char smem[];
    const uint32_t sb = smem_u32(smem);
    const uint32_t data = sb + 1024;
    const int tid = threadIdx.x;
    const int lane = tid & 31, wid = tid >> 5;
    const int wm = wid >> 2, wn = wid & 3;
    const int n0 = blockIdx.x * 128;
    const int otile = blockIdx.y, o0 = otile * 128;
    const int bp = blockIdx.z, proj = bp % 3, b = bp / 3;

    const __half* Asrc = g_wp2 + (size_t)((proj * 2 + otile) * 4) * 8192;
    const __half* Bsrc = g_xt2 + ((size_t)(b * 4) * NPIX + n0) * 64;

    if (tid == 0) { MB_INIT(sb, 1); MB_INIT(sb + 8, 1); MB_INIT(sb + 16, 1); }
    __syncthreads();

    auto issue = [&](int s) {
        const uint32_t mb = sb + (s % 3) * 8;
        const uint32_t dst = data + (s % 3) * QKV_SLOT;
        MB_EXPECT(mb, 32768u);
        bulk_g2s(dst,         Asrc + (size_t)s * 8192,      16384u, mb);
        bulk_g2s(dst + 16384, Bsrc + (size_t)s * NPIX * 64, 16384u, mb);
    };
    if (tid == 0) { issue(0); issue(1); issue(2); }

    float acc[4][4][4];
    #pragma unroll
    for (int i = 0; i < 4; i++)
        #pragma unroll
        for (int j = 0; j < 4; j++)
            #pragma unroll
            for (int q = 0; q < 4; q++) acc[i][j][q] = 0.f;

    #pragma unroll 1
    for (int s = 0; s < 4; s++) {
        MB_WAIT(sb + (s % 3) * 8, (s / 3) & 1);
        const uint32_t ab = data + (s % 3) * QKV_SLOT;
        const uint32_t bb = ab + 16384;
        #pragma unroll
        for (int kh = 0; kh < 4; kh++) {
            uint32_t ah[4][4], bf[4][2];
            #pragma unroll
            for (int i = 0; i < 4; i++) {
                const int row = wm * 64 + i * 16 + (lane & 15);
                const int ch = (2 * kh + (lane >> 4)) ^ (row & 7);
                ldmat4(ah[i], ab + row * 128 + ch * 16);
            }
            #pragma unroll
            for (int jj = 0; jj < 2; jj++) {
                const int row = wn * 32 + jj * 16 + (lane & 7) + ((lane >> 4) << 3);
                const int ch = (2 * kh + ((lane >> 3) & 1)) ^ (row & 7);
                uint32_t r4[4];
                ldmat4(r4, bb + row * 128 + ch * 16);
                bf[2*jj][0] = r4[0]; bf[2*jj][1] = r4[1];
                bf[2*jj+1][0] = r4[2]; bf[2*jj+1][1] = r4[3];
            }
            #pragma unroll
            for (int i = 0; i < 4; i++)
                #pragma unroll
                for (int j = 0; j < 4; j++)
                    mma16816(acc[i][j], ah[i], bf[j]);
        }
        __syncthreads();
        if (tid == 0 && s + 3 < 4) issue(s + 3);
    }

    const float* bias = (proj == 0) ? bq : (proj == 1) ? bk : bv;
    if (proj < 2) {
        // fp16 token-major: Qt[b][t][e], e = d*64 + l
        __half* qt = ((proj == 0) ? g_qt : g_kt) + (size_t)b * 64 * 16384;
        #pragma unroll
        for (int i = 0; i < 4; i++) {
            const int r0 = o0 + wm * 64 + i * 16 + (lane >> 2);
            const float bb0 = bias[r0], bb1 = bias[r0 + 8];
            #pragma unroll
            for (int j = 0; j < 4; j++) {
                const int p = n0 + wn * 32 + j * 8 + 2 * (lane & 3);
                const int h = p >> 6, w = p & 63;
                const int t = ((h >> 3) << 3) + (w >> 3);
                const int l = ((h & 7) << 3) + (w & 7);
                __half2 v0 = __floats2half2_rn(acc[i][j][0] + bb0, acc[i][j][1] + bb0);
                __half2 v1 = __floats2half2_rn(acc[i][j][2] + bb1, acc[i][j][3] + bb1);
                *(__half2*)(qt + (size_t)t * 16384 + r0 * 64 + l) = v0;
                *(__half2*)(qt + (size_t)t * 16384 + (r0 + 8) * 64 + l) = v1;
            }
        }
    } else {
        float* dst = g_v + (size_t)b * ND * NPIX;
        #pragma unroll
        for (int i = 0; i < 4; i++) {
            const int r0 = o0 + wm * 64 + i * 16 + (lane >> 2);
            const float bb0 = bias[r0], bb1 = bias[r0 + 8];
            #pragma unroll
            for (int j = 0; j < 4; j++) {
                const int cb = n0 + wn * 32 + j * 8 + 2 * (lane & 3);
                float2 v0 = make_float2(acc[i][j][0] + bb0, acc[i][j][1] + bb0);
                float2 v1 = make_float2(acc[i][j][2] + bb1, acc[i][j][3] + bb1);
                *(float2*)(dst + (size_t)r0 * NPIX + cb) = v0;
                *(float2*)(dst + (size_t)(r0 + 8) * NPIX + cb) = v1;
            }
        }
    }
}

// ---------------- scores via mma: S_partial[b][slice] = Qt . Kt^T over 2048 e ----------------
// grid (8, 16), 256 thr; warp = wn(0..1: n32) x wm(0..3: m16); 32 k64 chunks, 3-stage cp.async
#define SC_STAGE 16384
#define SC_SMEM  (3*SC_STAGE)

__global__ void __launch_bounds__(256, 2) scores_mma_kernel()
{
    extern __shared__ char smem[];
    const uint32_t sbase = smem_u32(smem);
    const int tid = threadIdx.x;
    const int lane = tid & 31, wid = tid >> 5;
    const int wm = wid & 3, wn = wid >> 2;
    const int slice = blockIdx.x, b = blockIdx.y;
    const size_t eoff = (size_t)slice * 2048;

    const __half* Q = g_qt + (size_t)b * 64 * 16384 + eoff;
    const __half* K = g_kt + (size_t)b * 64 * 16384 + eoff;

    auto load_stage = [&](int ck, int buf) {
        const uint32_t stb = sbase + buf * SC_STAGE;
        #pragma unroll
        for (int q = 0; q < 2; q++) {
            const int idx = tid + q * 256;        // 0..511
            const int row = idx >> 3, c = idx & 7;
            const uint32_t so = row * 128 + ((c ^ (row & 7)) << 4);
            const size_t goff = (size_t)row * 16384 + ck * 64 + c * 8;
            cp16(stb + so,        Q + goff);
            cp16(stb + 8192 + so, K + goff);
        }
        CP_COMMIT();
    };

    float acc[4][4];
    #pragma unroll
    for (int j = 0; j < 4; j++)
        #pragma unroll
        for (int q = 0; q < 4; q++) acc[j][q] = 0.f;

    load_stage(0, 0);
    load_stage(1, 1);
    #pragma unroll 1
    for (int s = 0; s < 32; s++) {
        if (s + 1 < 32) { CP_WAIT1(); } else { CP_WAIT0(); }
        __syncthreads();
        if (s + 2 < 32) load_stage(s + 2, (s + 2) % 3);
        const uint32_t qb = sbase + (s % 3) * SC_STAGE;
        const uint32_t kb = qb + 8192;
        #pragma unroll
        for (int kh = 0; kh < 4; kh++) {
            uint32_t ah[4], bf[4][2];
            {
                const int row = wm * 16 + (lane & 15);
                const int ch = (2 * kh + (lane >> 4)) ^ (row & 7);
                ldmat4(ah, qb + row * 128 + ch * 16);
            }
            #pragma unroll
            for (int jj = 0; jj < 2; jj++) {
                const int row = wn * 32 + jj * 16 + (lane & 7) + ((lane >> 4) << 3);
                const int ch = (2 * kh + ((lane >> 3) & 1)) ^ (row & 7);
                uint32_t r4[4];
                ldmat4(r4, kb + row * 128 + ch * 16);
                bf[2*jj][0] = r4[0]; bf[2*jj][1] = r4[1];
                bf[2*jj+1][0] = r4[2]; bf[2*jj+1][1] = r4[3];
            }
            #pragma unroll
            for (int j = 0; j < 4; j++)
                mma16816(acc[j], ah, bf[j]);
        }
        __syncthreads();
    }

    float* dst = g_spart + ((size_t)(b * 8 + slice)) * 4096;
    #pragma unroll
    for (int j = 0; j < 4; j++) {
        const int r0 = wm * 16 + (lane >> 2);
        const int cb = wn * 32 + j * 8 + 2 * (lane & 3);
        *(float2*)(dst + r0 * 64 + cb)       = make_float2(acc[j][0], acc[j][1]);
        *(float2*)(dst + (r0 + 8) * 64 + cb) = make_float2(acc[j][2], acc[j][3]);
    }
}

// ---------------- softmax (sums 8 slice partials) ----------------
__global__ void __launch_bounds__(64) softmax_kernel()
{
    const int b = blockIdx.x;
    const int t = threadIdx.x;
    const float scale = 1.0f / 128.0f;
    float v[64];
    #pragma unroll
    for (int u = 0; u < 64; u++) v[u] = 0.f;
    #pragma unroll 2
    for (int sl = 0; sl < 8; sl++) {
        const float* row = g_spart + ((size_t)(b * 8 + sl)) * 4096 + t * 64;
        #pragma unroll
        for (int u = 0; u < 64; u++) v[u] += row[u];
    }
    float m = -1e30f;
    #pragma unroll
    for (int u = 0; u < 64; u++) { v[u] *= scale; m = fmaxf(m, v[u]); }
    float s = 0.f;
    #pragma unroll
    for (int u = 0; u < 64; u++) { v[u] = __expf(v[u] - m); s += v[u]; }
    const float inv = 1.0f / s;
    float* arow = g_attn + b * 4096 + t * 64;
    #pragma unroll
    for (int u = 0; u < 64; u++) arow[u] = v[u] * inv;
}

// ---------------- av: out = attn @ V, writes conv-ready fp16 swizzled layout ----------------
__global__ void __launch_bounds__(256) av_kernel()
{
    const int h  = blockIdx.x;
    const int d0 = blockIdx.y * 16;
    const int b  = blockIdx.z;
    const int tid = threadIdx.x;

    __shared__ float attn_s[8][64];
    __shared__ float Vs[16][8][64];

    for (int idx = tid; idx < 512; idx += 256) {
        const int r = idx >> 6, j = idx & 63;
        attn_s[r][j] = g_attn[b * 4096 + ((h >> 3) * 8 + r) * 64 + j];
    }
    for (int idx = tid; idx < 8192; idx += 256) {
        const int dl = idx >> 9, j2 = (idx >> 6) & 7, w = idx & 63;
        Vs[dl][j2][w] = g_v[(((size_t)b * ND + d0 + dl) * 64 + j2 * 8 + (h & 7)) * 64 + w];
    }
    __syncthreads();

    const int dg = (tid >> 6) * 4;
    const int w  = tid & 63;
    float acc[4] = {0.f, 0.f, 0.f, 0.f};
    #pragma unroll 8
    for (int j = 0; j < 64; j++) {
        const float a = attn_s[w >> 3][j];
        const int col = ((j & 7) << 3) | (w & 7);
        #pragma unroll
        for (int q = 0; q < 4; q++) acc[q] += a * Vs[dg + q][j >> 3][col];
    }
    // write fp16 pre-swizzled conv-input layout
    const int pix = h * 64 + w;
    const int dbase = d0 + dg;               // multiple of 4
    const int chunk = dbase >> 6, cl = dbase & 63;
    const size_t off = ((size_t)(b * 4 + chunk) * NPIX + pix) * 64
                     + (((cl >> 3) ^ (pix & 7)) << 3) + (cl & 7);
    __half2 p0 = __floats2half2_rn(acc[0], acc[1]);
    __half2 p1 = __floats2half2_rn(acc[2], acc[3]);
    uint2 pk;
    pk.x = *(uint32_t*)&p0;
    pk.y = *(uint32_t*)&p1;
    *(uint2*)(g_aot2 + off) = pk;
}

// ---------------- conv 3x3: bulk pipeline + halo reuse + BN + LeakyReLU ----------------
#define CV_A_SLOT  16384
#define CV_HALO    (1024 + 3*CV_A_SLOT)
#define CV_SMEM    (CV_HALO + 33792)

__global__ void __launch_bounds__(256, 2) conv_mma_kernel(
    const float* __restrict__ b_out, const float* __restrict__ gamma,
    const float* __restrict__ beta,  const float* __restrict__ bn_mean,
    const float* __restrict__ bn_var, float* __restrict__ out)
{
    extern __shared__ char smem[];
    const uint32_t sb = smem_u32(smem);
    const uint32_t data = sb + 1024;
    const uint32_t halo = sb + CV_HALO;
    const int tid = threadIdx.x;
    const int lane = tid & 31, wid = tid >> 5;
    const int wm = wid >> 2, wn = wid & 3;
    const int pt = blockIdx.x;
    const int otile = blockIdx.y, o0 = otile * 128;
    const int b = blockIdx.z;
    const int h0 = pt * 2, n0 = pt * 128;

    const __half* Bbase = g_aot2 + (size_t)(b * 4) * NPIX * 64;

    if (tid == 0) { MB_INIT(sb, 1); MB_INIT(sb + 8, 1); MB_INIT(sb + 16, 1); MB_INIT(sb + 24, 1); }
    {
        const int4 z = make_int4(0, 0, 0, 0);
        for (int idx = tid; idx < 2112; idx += 256)
            *(int4*)(smem + CV_HALO + idx * 16) = z;
    }
    __syncthreads();

    auto issueA = [&](int s) {
        const int khw = s % 9, chunk = s / 9;
        const uint32_t mb = sb + (s % 3) * 8;
        MB_EXPECT(mb, 16384u);
        bulk_g2s(data + (s % 3) * CV_A_SLOT,
                 g_wc2 + (size_t)((khw * 2 + otile) * 4 + chunk) * 8192, 16384u, mb);
    };
    auto issueHalo = [&](int chunk) {
        const uint32_t mb = sb + 24;
        uint32_t bytes = 0;
        #pragma unroll
        for (int hr = 0; hr < 4; hr++) {
            const int h2 = h0 - 1 + hr;
            if ((unsigned)h2 < 64u) bytes += 8192u;
        }
        MB_EXPECT(mb, bytes);
        #pragma unroll
        for (int hr = 0; hr < 4; hr++) {
            const int h2 = h0 - 1 + hr;
            if ((unsigned)h2 < 64u)
                bulk_g2s(halo + hr * 8448 + 128,
                         Bbase + ((size_t)chunk * NPIX + h2 * 64) * 64, 8192u, mb);
        }
    };
    if (tid == 0) { issueHalo(0); issueA(0); issueA(1); issueA(2); }

    float acc[4][4][4];
    #pragma unroll
    for (int i = 0; i < 4; i++)
        #pragma unroll
        for (int j = 0; j < 4; j++)
            #pragma unroll
            for (int q = 0; q < 4; q++) acc[i][j][q] = 0.f;

    #pragma unroll 1
    for (int s = 0; s < 36; s++) {
        const int khw = s % 9, chunk = s / 9;
        MB_WAIT(sb + (s % 3) * 8, (s / 3) & 1);
        if (khw == 0) MB_WAIT(sb + 24, chunk & 1);
        const int dh = khw / 3 - 1, dw = khw % 3 - 1;
        const uint32_t ab = data + (s % 3) * CV_A_SLOT;
        #pragma unroll
        for (int kh = 0; kh < 4; kh++) {
            uint32_t ah[4][4], bf[4][2];
            #pragma unroll
            for (int i = 0; i < 4; i++) {
                const int row = wm * 64 + i * 16 + (lane & 15);
                const int ch = (2 * kh + (lane >> 4)) ^ (row & 7);
                ldmat4(ah[i], ab + row * 128 + ch * 16);
            }
            #pragma unroll
            for (int jj = 0; jj < 2; jj++) {
                const int p = wn * 32 + jj * 16 + (lane & 7) + ((lane >> 4) << 3);
                const int w2 = (p & 63) + dw;
                const int er = (p >> 6) + dh + 1;
                const int e = er * 66 + w2 + 1;
                const int ch = (2 * kh + ((lane >> 3) & 1)) ^ (w2 & 7);
                uint32_t r4[4];
                ldmat4(r4, halo + e * 128 + ch * 16);
                bf[2*jj][0] = r4[0]; bf[2*jj][1] = r4[1];
                bf[2*jj+1][0] = r4[2]; bf[2*jj+1][1] = r4[3];
            }
            #pragma unroll
            for (int i = 0; i < 4; i++)
                #pragma unroll
                for (int j = 0; j < 4; j++)
                    mma16816(acc[i][j], ah[i], bf[j]);
        }
        __syncthreads();
        if (tid == 0) {
            if (s + 3 < 36) issueA(s + 3);
            if (khw == 8 && chunk < 3) issueHalo(chunk + 1);
        }
    }

    float* dst = out + (size_t)b * ND * NPIX;
    #pragma unroll
    for (int i = 0; i < 4; i++) {
        const int r0 = o0 + wm * 64 + i * 16 + (lane >> 2);
        const float sc0 = gamma[r0]     * rsqrtf(bn_var[r0]     + 1e-5f);
        const float sc1 = gamma[r0 + 8] * rsqrtf(bn_var[r0 + 8] + 1e-5f);
        const float ad0 = (b_out[r0]     - bn_mean[r0])     * sc0 + beta[r0];
        const float ad1 = (b_out[r0 + 8] - bn_mean[r0 + 8]) * sc1 + beta[r0 + 8];
        #pragma unroll
        for (int j = 0; j < 4; j++) {
            const int cb = n0 + wn * 32 + j * 8 + 2 * (lane & 3);
            float t0 = acc[i][j][0] * sc0 + ad0;
            float t1 = acc[i][j][1] * sc0 + ad0;
            float t2 = acc[i][j][2] * sc1 + ad1;
            float t3 = acc[i][j][3] * sc1 + ad1;
            float2 v0 = make_float2((t0 >= 0.f) ? t0 : 0.2f * t0,
                                    (t1 >= 0.f) ? t1 : 0.2f * t1);
            float2 v1 = make_float2((t2 >= 0.f) ? t2 : 0.2f * t2,
                                    (t3 >= 0.f) ? t3 : 0.2f * t3);
            *(float2*)(dst + (size_t)r0 * NPIX + cb) = v0;
            *(float2*)(dst + (size_t)(r0 + 8) * NPIX + cb) = v1;
        }
    }
}

// ---------------- host ----------------
extern "C" void kernel_launch(void* const* d_in, const int* in_sizes, int n_in,
                              void* d_out, int out_size)
{
    const float* x       = (const float*)d_in[0];
    const float* wq      = (const float*)d_in[1];
    const float* bq      = (const float*)d_in[2];
    const float* wk      = (const float*)d_in[3];
    const float* bk      = (const float*)d_in[4];
    const float* wv      = (const float*)d_in[5];
    const float* bv      = (const float*)d_in[6];
    const float* w_out   = (const float*)d_in[7];
    const float* b_out   = (const float*)d_in[8];
    const float* gamma   = (const float*)d_in[9];
    const float* beta    = (const float*)d_in[10];
    const float* bn_mean = (const float*)d_in[11];
    const float* bn_var  = (const float*)d_in[12];
    float* out = (float*)d_out;

    cudaFuncSetAttribute(qkv_mma_kernel,    cudaFuncAttributeMaxDynamicSharedMemorySize, QKV_SMEM);
    cudaFuncSetAttribute(scores_mma_kernel, cudaFuncAttributeMaxDynamicSharedMemorySize, SC_SMEM);
    cudaFuncSetAttribute(conv_mma_kernel,   cudaFuncAttributeMaxDynamicSharedMemorySize, CV_SMEM);

    convert_wqkv_kernel <<<768,  256>>>(wq, wk, wv);
    convert_wconv_kernel<<<2304, 256>>>(w_out);
    convert_x_kernel<<<dim3(128, 8, 16), 256>>>(x);

    qkv_mma_kernel<<<dim3(32, 2, 48), 256, QKV_SMEM>>>(bq, bk, bv);

    scores_mma_kernel<<<dim3(8, 16), 256, SC_SMEM>>>();
    softmax_kernel<<<16, 64>>>();
    av_kernel<<<dim3(64, 16, 16), 256>>>();

    conv_mma_kernel<<<dim3(32, 2, 16), 256, CV_SMEM>>>(b_out, gamma, beta, bn_mean, bn_var, out);
}

// round 10
// speedup vs baseline: 1.8829x; 1.3532x over previous
#include <cuda_runtime.h>
#include <cuda_fp16.h>
#include <cstdint>
#include <math.h>

#define NB 16
#define ND 256
#define NPIX 4096

// ---------------- global scratch (allocation-free) ----------------
__device__ float g_spart[NB*8*64*64];                    // score partials per e-slice
__device__ __align__(16) __half g_attn_h[NB*64*64];      // attn hi fp16 [b][t][u]
__device__ __align__(16) __half g_attn_l[NB*64*64];      // attn lo fp16

__device__ __align__(16) __half g_qt [NB*64*16384];      // Q token-major [b][t][e]
__device__ __align__(16) __half g_kt [NB*64*16384];      // K token-major [b][t][e]
__device__ __align__(16) __half g_vt [NB*64*16384];      // V hi token-major [b][u][e]
__device__ __align__(16) __half g_vtl[NB*64*16384];      // V lo token-major
__device__ __align__(16) __half g_xt2 [NB*4*NPIX*64];    // x  [b][chunk][pix][64c] swizzled
__device__ __align__(16) __half g_aot2[NB*4*NPIX*64];    // attn-out, conv input layout
__device__ __align__(16) __half g_wp2 [3*2*4*128*64];    // [proj][otile][chunk][o128][64c]
__device__ __align__(16) __half g_wc2 [9*2*4*128*64];    // [khw][otile][chunk][o128][64c]

// ---------------- helpers ----------------
__device__ __forceinline__ uint32_t smem_u32(const void* p){
    uint32_t a;
    asm("{ .reg .u64 t; cvta.to.shared.u64 t, %1; cvt.u32.u64 %0, t; }" : "=r"(a) : "l"(p));
    return a;
}
#define MB_INIT(mb, n) asm volatile("mbarrier.init.shared.b64 [%0], %1;" :: "r"(mb), "r"(n) : "memory")
#define MB_EXPECT(mb, bytes) asm volatile("mbarrier.arrive.expect_tx.shared.b64 _, [%0], %1;" :: "r"(mb), "r"(bytes) : "memory")

__device__ __forceinline__ void bulk_g2s(uint32_t dst, const void* src, uint32_t bytes, uint32_t mbar){
    asm volatile("{ .reg .u64 g; cvta.to.global.u64 g, %1;\n\t"
        "cp.async.bulk.shared::cluster.global.mbarrier::complete_tx::bytes [%0], [g], %2, [%3]; }"
        :: "r"(dst), "l"(src), "r"(bytes), "r"(mbar) : "memory");
}

#define MB_WAIT(mb, ph) do { \
    uint32_t _m = (mb); uint32_t _p = (uint32_t)(ph); uint32_t _d; \
    asm volatile("{\n\t.reg .pred p;\n\t" \
        "mbarrier.try_wait.parity.acquire.cta.shared::cta.b64 p, [%1], %2;\n\t" \
        "selp.b32 %0, 1, 0, p;\n\t}" : "=r"(_d) : "r"(_m), "r"(_p) : "memory"); \
    if (!_d) { \
        asm volatile("{\n\t.reg .pred P1;\n\t" \
            "WAIT_LOOP_%=:\n\t" \
            "mbarrier.try_wait.parity.acquire.cta.shared::cta.b64 P1, [%0], %1, 0x989680;\n\t" \
            "@P1 bra.uni WAIT_DONE_%=;\n\t" \
            "bra.uni WAIT_LOOP_%=;\n\t" \
            "WAIT_DONE_%=:\n\t}" :: "r"(_m), "r"(_p) : "memory"); \
    } \
} while(0)

__device__ __forceinline__ void cp16(uint32_t saddr, const void* gaddr){
    asm volatile("cp.async.ca.shared.global [%0], [%1], 16;"
        :: "r"(saddr), "l"(gaddr));
}
#define CP_COMMIT() asm volatile("cp.async.commit_group;" ::: "memory")
#define CP_WAIT1()  asm volatile("cp.async.wait_group 1;" ::: "memory")
#define CP_WAIT0()  asm volatile("cp.async.wait_group 0;" ::: "memory")

__device__ __forceinline__ void ldmat4(uint32_t* r, uint32_t addr){
    asm volatile("ldmatrix.sync.aligned.m8n8.x4.shared.b16 {%0,%1,%2,%3}, [%4];"
        : "=r"(r[0]), "=r"(r[1]), "=r"(r[2]), "=r"(r[3]) : "r"(addr));
}
__device__ __forceinline__ void ldmat4t(uint32_t* r, uint32_t addr){
    asm volatile("ldmatrix.sync.aligned.m8n8.x4.trans.shared.b16 {%0,%1,%2,%3}, [%4];"
        : "=r"(r[0]), "=r"(r[1]), "=r"(r[2]), "=r"(r[3]) : "r"(addr));
}
__device__ __forceinline__ void mma16816(float* d, const uint32_t* a, const uint32_t* b){
    asm volatile("mma.sync.aligned.m16n8k16.row.col.f32.f16.f16.f32 "
        "{%0,%1,%2,%3}, {%4,%5,%6,%7}, {%8,%9}, {%0,%1,%2,%3};"
        : "+f"(d[0]), "+f"(d[1]), "+f"(d[2]), "+f"(d[3])
        : "r"(a[0]), "r"(a[1]), "r"(a[2]), "r"(a[3]), "r"(b[0]), "r"(b[1]));
}

// ---------------- converters ----------------
__global__ void __launch_bounds__(256) convert_x_kernel(const float* __restrict__ xsrc)
{
    const int b = blockIdx.z, c0 = blockIdx.y * 32, p0 = blockIdx.x * 32;
    __shared__ float tile[32][33];
    const int tx = threadIdx.x & 31, ty = threadIdx.x >> 5;
    const float* s = xsrc + ((size_t)b * ND + c0) * NPIX + p0;
    #pragma unroll
    for (int i = 0; i < 32; i += 8)
        tile[ty + i][tx] = s[(size_t)(ty + i) * NPIX + tx];
    __syncthreads();
    #pragma unroll
    for (int i = 0; i < 32; i += 8) {
        const int pix = p0 + ty + i;
        const int c = c0 + tx;
        const int chunk = c >> 6, cl = c & 63;
        size_t di = ((size_t)(b * 4 + chunk) * NPIX + pix) * 64
                  + (((cl >> 3) ^ (pix & 7)) << 3) + (cl & 7);
        g_xt2[di] = __float2half_rn(tile[tx][ty + i]);
    }
}

__global__ void __launch_bounds__(256) convert_wqkv_kernel(
    const float* __restrict__ wq, const float* __restrict__ wk, const float* __restrict__ wv)
{
    int i = blockIdx.x * 256 + threadIdx.x;
    const float* w = (i < 65536) ? wq : (i < 131072) ? wk : wv;
    const float v = w[i & 65535];
    const int proj = i >> 16, r = i & 65535;
    const int o_g = r >> 8, c_g = r & 255;
    const int otile = o_g >> 7, o = o_g & 127, chunk = c_g >> 6, c = c_g & 63;
    const size_t pos = (size_t)(((proj * 2 + otile) * 4 + chunk)) * 8192
                     + (o << 6) + (((c >> 3) ^ (o & 7)) << 3) + (c & 7);
    g_wp2[pos] = __float2half_rn(v);
}

__global__ void __launch_bounds__(256) convert_wconv_kernel(const float* __restrict__ w_out)
{
    int i = blockIdx.x * 256 + threadIdx.x;
    const float v = w_out[i];
    const int o_g = i / 2304;
    const int rem = i - o_g * 2304;
    const int c_g = rem / 9, khw = rem - (rem / 9) * 9;
    const int otile = o_g >> 7, o = o_g & 127, chunk = c_g >> 6, c = c_g & 63;
    const size_t pos = (size_t)(((khw * 2 + otile) * 4 + chunk)) * 8192
                     + (o << 6) + (((c >> 3) ^ (o & 7)) << 3) + (c & 7);
    g_wc2[pos] = __float2half_rn(v);
}

// ---------------- QKV GEMM: bulk pipeline; Q/K fp16, V hi+lo fp16 token-major ----------------
#define QKV_SLOT  32768
#define QKV_SMEM  (1024 + 3*QKV_SLOT)

__global__ void __launch_bounds__(256, 2) qkv_mma_kernel(
    const float* __restrict__ bq, const float* __restrict__ bk, const float* __restrict__ bv)
{
    extern __shared__ char smem[];
    const uint32_t sb = smem_u32(smem);
    const uint32_t data = sb + 1024;
    const int tid = threadIdx.x;
    const int lane = tid & 31, wid = tid >> 5;
    const int wm = wid >> 2, wn = wid & 3;
    const int n0 = blockIdx.x * 128;
    const int otile = blockIdx.y, o0 = otile * 128;
    const int bp = blockIdx.z, proj = bp % 3, b = bp / 3;

    const __half* Asrc = g_wp2 + (size_t)((proj * 2 + otile) * 4) * 8192;
    const __half* Bsrc = g_xt2 + ((size_t)(b * 4) * NPIX + n0) * 64;

    if (tid == 0) { MB_INIT(sb, 1); MB_INIT(sb + 8, 1); MB_INIT(sb + 16, 1); }
    __syncthreads();

    auto issue = [&](int s) {
        const uint32_t mb = sb + (s % 3) * 8;
        const uint32_t dst = data + (s % 3) * QKV_SLOT;
        MB_EXPECT(mb, 32768u);
        bulk_g2s(dst,         Asrc + (size_t)s * 8192,      16384u, mb);
        bulk_g2s(dst + 16384, Bsrc + (size_t)s * NPIX * 64, 16384u, mb);
    };
    if (tid == 0) { issue(0); issue(1); issue(2); }

    float acc[4][4][4];
    #pragma unroll
    for (int i = 0; i < 4; i++)
        #pragma unroll
        for (int j = 0; j < 4; j++)
            #pragma unroll
            for (int q = 0; q < 4; q++) acc[i][j][q] = 0.f;

    #pragma unroll 1
    for (int s = 0; s < 4; s++) {
        MB_WAIT(sb + (s % 3) * 8, (s / 3) & 1);
        const uint32_t ab = data + (s % 3) * QKV_SLOT;
        const uint32_t bb = ab + 16384;
        #pragma unroll
        for (int kh = 0; kh < 4; kh++) {
            uint32_t ah[4][4], bf[4][2];
            #pragma unroll
            for (int i = 0; i < 4; i++) {
                const int row = wm * 64 + i * 16 + (lane & 15);
                const int ch = (2 * kh + (lane >> 4)) ^ (row & 7);
                ldmat4(ah[i], ab + row * 128 + ch * 16);
            }
            #pragma unroll
            for (int jj = 0; jj < 2; jj++) {
                const int row = wn * 32 + jj * 16 + (lane & 7) + ((lane >> 4) << 3);
                const int ch = (2 * kh + ((lane >> 3) & 1)) ^ (row & 7);
                uint32_t r4[4];
                ldmat4(r4, bb + row * 128 + ch * 16);
                bf[2*jj][0] = r4[0]; bf[2*jj][1] = r4[1];
                bf[2*jj+1][0] = r4[2]; bf[2*jj+1][1] = r4[3];
            }
            #pragma unroll
            for (int i = 0; i < 4; i++)
                #pragma unroll
                for (int j = 0; j < 4; j++)
                    mma16816(acc[i][j], ah[i], bf[j]);
        }
        __syncthreads();
        if (tid == 0 && s + 3 < 4) issue(s + 3);
    }

    const float* bias = (proj == 0) ? bq : (proj == 1) ? bk : bv;
    if (proj < 2) {
        __half* qt = ((proj == 0) ? g_qt : g_kt) + (size_t)b * 64 * 16384;
        #pragma unroll
        for (int i = 0; i < 4; i++) {
            const int r0 = o0 + wm * 64 + i * 16 + (lane >> 2);
            const float bb0 = bias[r0], bb1 = bias[r0 + 8];
            #pragma unroll
            for (int j = 0; j < 4; j++) {
                const int p = n0 + wn * 32 + j * 8 + 2 * (lane & 3);
                const int h = p >> 6, w = p & 63;
                const int t = ((h >> 3) << 3) + (w >> 3);
                const int l = ((h & 7) << 3) + (w & 7);
                __half2 v0 = __floats2half2_rn(acc[i][j][0] + bb0, acc[i][j][1] + bb0);
                __half2 v1 = __floats2half2_rn(acc[i][j][2] + bb1, acc[i][j][3] + bb1);
                *(__half2*)(qt + (size_t)t * 16384 + r0 * 64 + l) = v0;
                *(__half2*)(qt + (size_t)t * 16384 + (r0 + 8) * 64 + l) = v1;
            }
        }
    } else {
        __half* vh = g_vt  + (size_t)b * 64 * 16384;
        __half* vl = g_vtl + (size_t)b * 64 * 16384;
        #pragma unroll
        for (int i = 0; i < 4; i++) {
            const int r0 = o0 + wm * 64 + i * 16 + (lane >> 2);
            const float bb0 = bias[r0], bb1 = bias[r0 + 8];
            #pragma unroll
            for (int j = 0; j < 4; j++) {
                const int p = n0 + wn * 32 + j * 8 + 2 * (lane & 3);
                const int h = p >> 6, w = p & 63;
                const int t = ((h >> 3) << 3) + (w >> 3);
                const int l = ((h & 7) << 3) + (w & 7);
                float f0 = acc[i][j][0] + bb0, f1 = acc[i][j][1] + bb0;
                float f2 = acc[i][j][2] + bb1, f3 = acc[i][j][3] + bb1;
                __half h0 = __float2half_rn(f0), h1 = __float2half_rn(f1);
                __half h2 = __float2half_rn(f2), h3 = __float2half_rn(f3);
                __half2 hv0; hv0.x = h0; hv0.y = h1;
                __half2 hv1; hv1.x = h2; hv1.y = h3;
                __half2 lv0 = __floats2half2_rn(f0 - __half2float(h0), f1 - __half2float(h1));
                __half2 lv1 = __floats2half2_rn(f2 - __half2float(h2), f3 - __half2float(h3));
                *(__half2*)(vh + (size_t)t * 16384 + r0 * 64 + l) = hv0;
                *(__half2*)(vh + (size_t)t * 16384 + (r0 + 8) * 64 + l) = hv1;
                *(__half2*)(vl + (size_t)t * 16384 + r0 * 64 + l) = lv0;
                *(__half2*)(vl + (size_t)t * 16384 + (r0 + 8) * 64 + l) = lv1;
            }
        }
    }
}

// ---------------- scores via mma ----------------
#define SC_STAGE 16384
#define SC_SMEM  (3*SC_STAGE)

__global__ void __launch_bounds__(256, 2) scores_mma_kernel()
{
    extern __shared__ char smem[];
    const uint32_t sbase = smem_u32(smem);
    const int tid = threadIdx.x;
    const int lane = tid & 31, wid = tid >> 5;
    const int wm = wid & 3, wn = wid >> 2;
    const int slice = blockIdx.x, b = blockIdx.y;
    const size_t eoff = (size_t)slice * 2048;

    const __half* Q = g_qt + (size_t)b * 64 * 16384 + eoff;
    const __half* K = g_kt + (size_t)b * 64 * 16384 + eoff;

    auto load_stage = [&](int ck, int buf) {
        const uint32_t stb = sbase + buf * SC_STAGE;
        #pragma unroll
        for (int q = 0; q < 2; q++) {
            const int idx = tid + q * 256;
            const int row = idx >> 3, c = idx & 7;
            const uint32_t so = row * 128 + ((c ^ (row & 7)) << 4);
            const size_t goff = (size_t)row * 16384 + ck * 64 + c * 8;
            cp16(stb + so,        Q + goff);
            cp16(stb + 8192 + so, K + goff);
        }
        CP_COMMIT();
    };

    float acc[4][4];
    #pragma unroll
    for (int j = 0; j < 4; j++)
        #pragma unroll
        for (int q = 0; q < 4; q++) acc[j][q] = 0.f;

    load_stage(0, 0);
    load_stage(1, 1);
    #pragma unroll 1
    for (int s = 0; s < 32; s++) {
        if (s + 1 < 32) { CP_WAIT1(); } else { CP_WAIT0(); }
        __syncthreads();
        if (s + 2 < 32) load_stage(s + 2, (s + 2) % 3);
        const uint32_t qb = sbase + (s % 3) * SC_STAGE;
        const uint32_t kb = qb + 8192;
        #pragma unroll
        for (int kh = 0; kh < 4; kh++) {
            uint32_t ah[4], bf[4][2];
            {
                const int row = wm * 16 + (lane & 15);
                const int ch = (2 * kh + (lane >> 4)) ^ (row & 7);
                ldmat4(ah, qb + row * 128 + ch * 16);
            }
            #pragma unroll
            for (int jj = 0; jj < 2; jj++) {
                const int row = wn * 32 + jj * 16 + (lane & 7) + ((lane >> 4) << 3);
                const int ch = (2 * kh + ((lane >> 3) & 1)) ^ (row & 7);
                uint32_t r4[4];
                ldmat4(r4, kb + row * 128 + ch * 16);
                bf[2*jj][0] = r4[0]; bf[2*jj][1] = r4[1];
                bf[2*jj+1][0] = r4[2]; bf[2*jj+1][1] = r4[3];
            }
            #pragma unroll
            for (int j = 0; j < 4; j++)
                mma16816(acc[j], ah, bf[j]);
        }
        __syncthreads();
    }

    float* dst = g_spart + ((size_t)(b * 8 + slice)) * 4096;
    #pragma unroll
    for (int j = 0; j < 4; j++) {
        const int r0 = wm * 16 + (lane >> 2);
        const int cb = wn * 32 + j * 8 + 2 * (lane & 3);
        *(float2*)(dst + r0 * 64 + cb)       = make_float2(acc[j][0], acc[j][1]);
        *(float2*)(dst + (r0 + 8) * 64 + cb) = make_float2(acc[j][2], acc[j][3]);
    }
}

// ---------------- softmax -> attn hi/lo fp16 ----------------
__global__ void __launch_bounds__(64) softmax_kernel()
{
    const int b = blockIdx.x;
    const int t = threadIdx.x;
    const float scale = 1.0f / 128.0f;
    float v[64];
    #pragma unroll
    for (int u = 0; u < 64; u++) v[u] = 0.f;
    #pragma unroll 2
    for (int sl = 0; sl < 8; sl++) {
        const float* row = g_spart + ((size_t)(b * 8 + sl)) * 4096 + t * 64;
        #pragma unroll
        for (int u = 0; u < 64; u++) v[u] += row[u];
    }
    float m = -1e30f;
    #pragma unroll
    for (int u = 0; u < 64; u++) { v[u] *= scale; m = fmaxf(m, v[u]); }
    float s = 0.f;
    #pragma unroll
    for (int u = 0; u < 64; u++) { v[u] = __expf(v[u] - m); s += v[u]; }
    const float inv = 1.0f / s;
    __half* hrow = g_attn_h + b * 4096 + t * 64;
    __half* lrow = g_attn_l + b * 4096 + t * 64;
    #pragma unroll
    for (int u = 0; u < 64; u += 2) {
        float f0 = v[u] * inv, f1 = v[u+1] * inv;
        __half h0 = __float2half_rn(f0), h1 = __float2half_rn(f1);
        __half2 hh; hh.x = h0; hh.y = h1;
        *(__half2*)(hrow + u) = hh;
        *(__half2*)(lrow + u) = __floats2half2_rn(f0 - __half2float(h0), f1 - __half2float(h1));
    }
}

// ---------------- av via mma (4-term hi/lo): Out = attn @ Vt; scatter to conv layout ----------------
// smem: Ah 8KB @0, Al 8KB @8192, Vh 32KB @16384, Vl 32KB @49152, Out 32KB @81920
#define AV_AL   8192
#define AV_VH   16384
#define AV_VL   49152
#define AV_OUT  81920
#define AV_SMEM 114688

__global__ void __launch_bounds__(256, 2) av_mma_kernel()
{
    extern __shared__ char smem[];
    const uint32_t sbase = smem_u32(smem);
    const int tid = threadIdx.x;
    const int lane = tid & 31, wid = tid >> 5;
    const int wm = wid >> 1, wn = wid & 1;      // warp tile: 16 t x 128 e
    const int et = blockIdx.x, b = blockIdx.y;
    const size_t e0 = (size_t)et * 256;

    // load attn hi/lo [64 t][64 u] and V hi/lo tile [64 u][256 e]
    {
        const __half* Ah = g_attn_h + (size_t)b * 4096;
        const __half* Al = g_attn_l + (size_t)b * 4096;
        const __half* Vh = g_vt  + (size_t)b * 64 * 16384 + e0;
        const __half* Vl = g_vtl + (size_t)b * 64 * 16384 + e0;
        #pragma unroll
        for (int q = 0; q < 2; q++) {
            const int idx = tid + q * 256;      // 0..511
            const int row = idx >> 3, c = idx & 7;
            const uint32_t so = row * 128 + ((c ^ (row & 7)) << 4);
            cp16(sbase + so,         Ah + (size_t)row * 64 + c * 8);
            cp16(sbase + AV_AL + so, Al + (size_t)row * 64 + c * 8);
        }
        #pragma unroll
        for (int q = 0; q < 8; q++) {
            const int idx = tid + q * 256;      // 0..2047
            const int row = idx >> 5, c = idx & 31;
            const int sw = (c & 24) | ((c & 7) ^ (row & 7));
            cp16(sbase + AV_VH + row * 512 + sw * 16, Vh + (size_t)row * 16384 + c * 8);
            cp16(sbase + AV_VL + row * 512 + sw * 16, Vl + (size_t)row * 16384 + c * 8);
        }
        CP_COMMIT();
        CP_WAIT0();
    }
    __syncthreads();

    float acc[16][4];
    #pragma unroll
    for (int j = 0; j < 16; j++)
        #pragma unroll
        for (int q = 0; q < 4; q++) acc[j][q] = 0.f;

    #pragma unroll
    for (int kh = 0; kh < 4; kh++) {
        uint32_t ahh[4], ahl[4];
        {
            const int row = wm * 16 + (lane & 15);
            const int ch = (2 * kh + (lane >> 4)) ^ (row & 7);
            ldmat4(ahh, sbase + row * 128 + ch * 16);
            ldmat4(ahl, sbase + AV_AL + row * 128 + ch * 16);
        }
        #pragma unroll
        for (int jj = 0; jj < 8; jj++) {
            const int u = kh * 16 + (lane & 15);
            const int c32 = wn * 16 + jj * 2 + (lane >> 4);
            const int sw = (c32 & 24) | ((c32 & 7) ^ (u & 7));
            uint32_t rh[4], rl[4];
            ldmat4t(rh, sbase + AV_VH + u * 512 + sw * 16);
            ldmat4t(rl, sbase + AV_VL + u * 512 + sw * 16);
            uint32_t bh0[2] = { rh[0], rh[1] }, bh1[2] = { rh[2], rh[3] };
            uint32_t bl0[2] = { rl[0], rl[1] }, bl1[2] = { rl[2], rl[3] };
            mma16816(acc[jj*2],   ahh, bh0);
            mma16816(acc[jj*2],   ahh, bl0);
            mma16816(acc[jj*2],   ahl, bh0);
            mma16816(acc[jj*2],   ahl, bl0);
            mma16816(acc[jj*2+1], ahh, bh1);
            mma16816(acc[jj*2+1], ahh, bl1);
            mma16816(acc[jj*2+1], ahl, bh1);
            mma16816(acc[jj*2+1], ahl, bl1);
        }
    }

    // stage Out[64 t][256 e] to smem (swizzled rows of 512B)
    #pragma unroll
    for (int j = 0; j < 16; j++) {
        const int t0 = wm * 16 + (lane >> 2);
        const int e  = wn * 128 + j * 8 + 2 * (lane & 3);
        const int c  = e >> 3;
        const int sw0 = (c & 24) | ((c & 7) ^ (t0 & 7));
        const int sw1 = (c & 24) | ((c & 7) ^ ((t0 + 8) & 7));
        __half2 v0 = __floats2half2_rn(acc[j][0], acc[j][1]);
        __half2 v1 = __floats2half2_rn(acc[j][2], acc[j][3]);
        *(__half2*)(smem + AV_OUT + t0 * 512 + sw0 * 16 + (e & 7) * 2) = v0;
        *(__half2*)(smem + AV_OUT + (t0 + 8) * 512 + sw1 * 16 + (e & 7) * 2) = v1;
    }
    __syncthreads();

    // scatter: per pixel, 4 channels (d' 0..3) -> one uint2 in g_aot2
    const int d0g = et * 4;
    const int chunk_g = d0g >> 6, cl0 = d0g & 63;
    __half* outg = g_aot2 + ((size_t)(b * 4 + chunk_g)) * NPIX * 64;
    #pragma unroll
    for (int p = 0; p < 16; p++) {
        const int pix = tid + p * 256;
        const int h = pix >> 6, w = pix & 63;
        const int t = ((h >> 3) << 3) + (w >> 3);
        const int l = ((h & 7) << 3) + (w & 7);
        uint32_t hv[4];
        #pragma unroll
        for (int dq = 0; dq < 4; dq++) {
            const int sw = dq * 8 + ((l >> 3) ^ (t & 7));
            hv[dq] = *(const uint16_t*)(smem + AV_OUT + t * 512 + sw * 16 + (l & 7) * 2);
        }
        uint2 pk;
        pk.x = hv[0] | (hv[1] << 16);
        pk.y = hv[2] | (hv[3] << 16);
        const size_t off = (size_t)pix * 64 + (((cl0 >> 3) ^ (pix & 7)) << 3) + (cl0 & 7);
        *(uint2*)(outg + off) = pk;
    }
}

// ---------------- conv 3x3: R7 proven bulk pipeline + halo reuse + BN + LeakyReLU ----------------
#define CV_A_SLOT  16384
#define CV_HALO    (1024 + 3*CV_A_SLOT)
#define CV_SMEM    (CV_HALO + 33792)

__global__ void __launch_bounds__(256, 2) conv_mma_kernel(
    const float* __restrict__ b_out, const float* __restrict__ gamma,
    const float* __restrict__ beta,  const float* __restrict__ bn_mean,
    const float* __restrict__ bn_var, float* __restrict__ out)
{
    extern __shared__ char smem[];
    const uint32_t sb = smem_u32(smem);
    const uint32_t data = sb + 1024;
    const uint32_t halo = sb + CV_HALO;
    const int tid = threadIdx.x;
    const int lane = tid & 31, wid = tid >> 5;
    const int wm = wid >> 2, wn = wid & 3;
    const int pt = blockIdx.x;
    const int otile = blockIdx.y, o0 = otile * 128;
    const int b = blockIdx.z;
    const int h0 = pt * 2, n0 = pt * 128;

    const __half* Bbase = g_aot2 + (size_t)(b * 4) * NPIX * 64;

    if (tid == 0) { MB_INIT(sb, 1); MB_INIT(sb + 8, 1); MB_INIT(sb + 16, 1); MB_INIT(sb + 24, 1); }
    {
        const int4 z = make_int4(0, 0, 0, 0);
        for (int idx = tid; idx < 2112; idx += 256)
            *(int4*)(smem + CV_HALO + idx * 16) = z;
    }
    __syncthreads();

    auto issueA = [&](int s) {
        const int khw = s % 9, chunk = s / 9;
        const uint32_t mb = sb + (s % 3) * 8;
        MB_EXPECT(mb, 16384u);
        bulk_g2s(data + (s % 3) * CV_A_SLOT,
                 g_wc2 + (size_t)((khw * 2 + otile) * 4 + chunk) * 8192, 16384u, mb);
    };
    auto issueHalo = [&](int chunk) {
        const uint32_t mb = sb + 24;
        uint32_t bytes = 0;
        #pragma unroll
        for (int hr = 0; hr < 4; hr++) {
            const int h2 = h0 - 1 + hr;
            if ((unsigned)h2 < 64u) bytes += 8192u;
        }
        MB_EXPECT(mb, bytes);
        #pragma unroll
        for (int hr = 0; hr < 4; hr++) {
            const int h2 = h0 - 1 + hr;
            if ((unsigned)h2 < 64u)
                bulk_g2s(halo + hr * 8448 + 128,
                         Bbase + ((size_t)chunk * NPIX + h2 * 64) * 64, 8192u, mb);
        }
    };
    if (tid == 0) { issueHalo(0); issueA(0); issueA(1); issueA(2); }

    float acc[4][4][4];
    #pragma unroll
    for (int i = 0; i < 4; i++)
        #pragma unroll
        for (int j = 0; j < 4; j++)
            #pragma unroll
            for (int q = 0; q < 4; q++) acc[i][j][q] = 0.f;

    #pragma unroll 1
    for (int s = 0; s < 36; s++) {
        const int khw = s % 9, chunk = s / 9;
        MB_WAIT(sb + (s % 3) * 8, (s / 3) & 1);
        if (khw == 0) MB_WAIT(sb + 24, chunk & 1);
        const int dh = khw / 3 - 1, dw = khw % 3 - 1;
        const uint32_t ab = data + (s % 3) * CV_A_SLOT;
        #pragma unroll
        for (int kh = 0; kh < 4; kh++) {
            uint32_t ah[4][4], bf[4][2];
            #pragma unroll
            for (int i = 0; i < 4; i++) {
                const int row = wm * 64 + i * 16 + (lane & 15);
                const int ch = (2 * kh + (lane >> 4)) ^ (row & 7);
                ldmat4(ah[i], ab + row * 128 + ch * 16);
            }
            #pragma unroll
            for (int jj = 0; jj < 2; jj++) {
                const int p = wn * 32 + jj * 16 + (lane & 7) + ((lane >> 4) << 3);
                const int w2 = (p & 63) + dw;
                const int er = (p >> 6) + dh + 1;
                const int e = er * 66 + w2 + 1;
                const int ch = (2 * kh + ((lane >> 3) & 1)) ^ (w2 & 7);
                uint32_t r4[4];
                ldmat4(r4, halo + e * 128 + ch * 16);
                bf[2*jj][0] = r4[0]; bf[2*jj][1] = r4[1];
                bf[2*jj+1][0] = r4[2]; bf[2*jj+1][1] = r4[3];
            }
            #pragma unroll
            for (int i = 0; i < 4; i++)
                #pragma unroll
                for (int j = 0; j < 4; j++)
                    mma16816(acc[i][j], ah[i], bf[j]);
        }
        __syncthreads();
        if (tid == 0) {
            if (s + 3 < 36) issueA(s + 3);
            if (khw == 8 && chunk < 3) issueHalo(chunk + 1);
        }
    }

    float* dst = out + (size_t)b * ND * NPIX;
    #pragma unroll
    for (int i = 0; i < 4; i++) {
        const int r0 = o0 + wm * 64 + i * 16 + (lane >> 2);
        const float sc0 = gamma[r0]     * rsqrtf(bn_var[r0]     + 1e-5f);
        const float sc1 = gamma[r0 + 8] * rsqrtf(bn_var[r0 + 8] + 1e-5f);
        const float ad0 = (b_out[r0]     - bn_mean[r0])     * sc0 + beta[r0];
        const float ad1 = (b_out[r0 + 8] - bn_mean[r0 + 8]) * sc1 + beta[r0 + 8];
        #pragma unroll
        for (int j = 0; j < 4; j++) {
            const int cb = n0 + wn * 32 + j * 8 + 2 * (lane & 3);
            float t0 = acc[i][j][0] * sc0 + ad0;
            float t1 = acc[i][j][1] * sc0 + ad0;
            float t2 = acc[i][j][2] * sc1 + ad1;
            float t3 = acc[i][j][3] * sc1 + ad1;
            float2 v0 = make_float2((t0 >= 0.f) ? t0 : 0.2f * t0,
                                    (t1 >= 0.f) ? t1 : 0.2f * t1);
            float2 v1 = make_float2((t2 >= 0.f) ? t2 : 0.2f * t2,
                                    (t3 >= 0.f) ? t3 : 0.2f * t3);
            *(float2*)(dst + (size_t)r0 * NPIX + cb) = v0;
            *(float2*)(dst + (size_t)(r0 + 8) * NPIX + cb) = v1;
        }
    }
}

// ---------------- host ----------------
extern "C" void kernel_launch(void* const* d_in, const int* in_sizes, int n_in,
                              void* d_out, int out_size)
{
    const float* x       = (const float*)d_in[0];
    const float* wq      = (const float*)d_in[1];
    const float* bq      = (const float*)d_in[2];
    const float* wk      = (const float*)d_in[3];
    const float* bk      = (const float*)d_in[4];
    const float* wv      = (const float*)d_in[5];
    const float* bv      = (const float*)d_in[6];
    const float* w_out   = (const float*)d_in[7];
    const float* b_out   = (const float*)d_in[8];
    const float* gamma   = (const float*)d_in[9];
    const float* beta    = (const float*)d_in[10];
    const float* bn_mean = (const float*)d_in[11];
    const float* bn_var  = (const float*)d_in[12];
    float* out = (float*)d_out;

    cudaFuncSetAttribute(qkv_mma_kernel,    cudaFuncAttributeMaxDynamicSharedMemorySize, QKV_SMEM);
    cudaFuncSetAttribute(scores_mma_kernel, cudaFuncAttributeMaxDynamicSharedMemorySize, SC_SMEM);
    cudaFuncSetAttribute(av_mma_kernel,     cudaFuncAttributeMaxDynamicSharedMemorySize, AV_SMEM);
    cudaFuncSetAttribute(conv_mma_kernel,   cudaFuncAttributeMaxDynamicSharedMemorySize, CV_SMEM);

    convert_wqkv_kernel <<<768,  256>>>(wq, wk, wv);
    convert_wconv_kernel<<<2304, 256>>>(w_out);
    convert_x_kernel<<<dim3(128, 8, 16), 256>>>(x);

    qkv_mma_kernel<<<dim3(32, 2, 48), 256, QKV_SMEM>>>(bq, bk, bv);

    scores_mma_kernel<<<dim3(8, 16), 256, SC_SMEM>>>();
    softmax_kernel<<<16, 64>>>();
    av_mma_kernel<<<dim3(64, 16), 256, AV_SMEM>>>();

    conv_mma_kernel<<<dim3(32, 2, 16), 256, CV_SMEM>>>(b_out, gamma, beta, bn_mean, bn_var, out);
}

// round 11
// speedup vs baseline: 1.8879x; 1.0027x over previous
#include <cuda_runtime.h>
#include <cuda_fp16.h>
#include <cstdint>
#include <math.h>

#define NB 16
#define ND 256
#define NPIX 4096

// ---------------- global scratch (allocation-free) ----------------
__device__ float g_spart[NB*8*64*64];                    // score partials per e-slice
__device__ __align__(16) __half g_attn_h[NB*64*64];      // attn hi fp16 [b][t][u]
__device__ __align__(16) __half g_attn_l[NB*64*64];      // attn lo fp16

__device__ __align__(16) __half g_qt [NB*64*16384];      // Q token-major [b][t][e]
__device__ __align__(16) __half g_kt [NB*64*16384];      // K token-major [b][t][e]
__device__ __align__(16) __half g_vt [NB*64*16384];      // V hi token-major [b][u][e]
__device__ __align__(16) __half g_vtl[NB*64*16384];      // V lo token-major
__device__ __align__(16) __half g_xt2 [NB*4*NPIX*64];    // x  [b][chunk][pix][64c] swizzled
__device__ __align__(16) __half g_aot2[NB*4*NPIX*64];    // attn-out, conv input layout
__device__ __align__(16) __half g_wp2 [3*2*4*128*64];    // [proj][otile][chunk][o128][64c]
__device__ __align__(16) __half g_wc2 [9*2*4*128*64];    // [khw][otile][chunk][o128][64c]

// ---------------- helpers ----------------
__device__ __forceinline__ uint32_t smem_u32(const void* p){
    uint32_t a;
    asm("{ .reg .u64 t; cvta.to.shared.u64 t, %1; cvt.u32.u64 %0, t; }" : "=r"(a) : "l"(p));
    return a;
}
#define MB_INIT(mb, n) asm volatile("mbarrier.init.shared.b64 [%0], %1;" :: "r"(mb), "r"(n) : "memory")
#define MB_EXPECT(mb, bytes) asm volatile("mbarrier.arrive.expect_tx.shared.b64 _, [%0], %1;" :: "r"(mb), "r"(bytes) : "memory")

__device__ __forceinline__ void bulk_g2s(uint32_t dst, const void* src, uint32_t bytes, uint32_t mbar){
    asm volatile("{ .reg .u64 g; cvta.to.global.u64 g, %1;\n\t"
        "cp.async.bulk.shared::cluster.global.mbarrier::complete_tx::bytes [%0], [g], %2, [%3]; }"
        :: "r"(dst), "l"(src), "r"(bytes), "r"(mbar) : "memory");
}

#define MB_WAIT(mb, ph) do { \
    uint32_t _m = (mb); uint32_t _p = (uint32_t)(ph); uint32_t _d; \
    asm volatile("{\n\t.reg .pred p;\n\t" \
        "mbarrier.try_wait.parity.acquire.cta.shared::cta.b64 p, [%1], %2;\n\t" \
        "selp.b32 %0, 1, 0, p;\n\t}" : "=r"(_d) : "r"(_m), "r"(_p) : "memory"); \
    if (!_d) { \
        asm volatile("{\n\t.reg .pred P1;\n\t" \
            "WAIT_LOOP_%=:\n\t" \
            "mbarrier.try_wait.parity.acquire.cta.shared::cta.b64 P1, [%0], %1, 0x989680;\n\t" \
            "@P1 bra.uni WAIT_DONE_%=;\n\t" \
            "bra.uni WAIT_LOOP_%=;\n\t" \
            "WAIT_DONE_%=:\n\t}" :: "r"(_m), "r"(_p) : "memory"); \
    } \
} while(0)

__device__ __forceinline__ void cp16(uint32_t saddr, const void* gaddr){
    asm volatile("cp.async.ca.shared.global [%0], [%1], 16;"
        :: "r"(saddr), "l"(gaddr));
}
#define CP_COMMIT() asm volatile("cp.async.commit_group;" ::: "memory")
#define CP_WAIT1()  asm volatile("cp.async.wait_group 1;" ::: "memory")
#define CP_WAIT0()  asm volatile("cp.async.wait_group 0;" ::: "memory")

__device__ __forceinline__ void ldmat4(uint32_t* r, uint32_t addr){
    asm volatile("ldmatrix.sync.aligned.m8n8.x4.shared.b16 {%0,%1,%2,%3}, [%4];"
        : "=r"(r[0]), "=r"(r[1]), "=r"(r[2]), "=r"(r[3]) : "r"(addr));
}
__device__ __forceinline__ void ldmat4t(uint32_t* r, uint32_t addr){
    asm volatile("ldmatrix.sync.aligned.m8n8.x4.trans.shared.b16 {%0,%1,%2,%3}, [%4];"
        : "=r"(r[0]), "=r"(r[1]), "=r"(r[2]), "=r"(r[3]) : "r"(addr));
}
__device__ __forceinline__ void mma16816(float* d, const uint32_t* a, const uint32_t* b){
    asm volatile("mma.sync.aligned.m16n8k16.row.col.f32.f16.f16.f32 "
        "{%0,%1,%2,%3}, {%4,%5,%6,%7}, {%8,%9}, {%0,%1,%2,%3};"
        : "+f"(d[0]), "+f"(d[1]), "+f"(d[2]), "+f"(d[3])
        : "r"(a[0]), "r"(a[1]), "r"(a[2]), "r"(a[3]), "r"(b[0]), "r"(b[1]));
}

// ---------------- converters ----------------
__global__ void __launch_bounds__(256) convert_x_kernel(const float* __restrict__ xsrc)
{
    const int b = blockIdx.z, c0 = blockIdx.y * 32, p0 = blockIdx.x * 32;
    __shared__ float tile[32][33];
    const int tx = threadIdx.x & 31, ty = threadIdx.x >> 5;
    const float* s = xsrc + ((size_t)b * ND + c0) * NPIX + p0;
    #pragma unroll
    for (int i = 0; i < 32; i += 8)
        tile[ty + i][tx] = s[(size_t)(ty + i) * NPIX + tx];
    __syncthreads();
    // paired-channel half2 stores
    const int cc = (threadIdx.x & 15) * 2;      // even channel offset 0..30
    const int pr = threadIdx.x >> 4;            // 0..15
    #pragma unroll
    for (int pass = 0; pass < 2; pass++) {
        const int prow = pr + pass * 16;
        const int pix = p0 + prow;
        const int c = c0 + cc;
        const int chunk = c >> 6, cl = c & 63;
        size_t di = ((size_t)(b * 4 + chunk) * NPIX + pix) * 64
                  + (((cl >> 3) ^ (pix & 7)) << 3) + (cl & 7);
        *(__half2*)(g_xt2 + di) = __floats2half2_rn(tile[cc][prow], tile[cc + 1][prow]);
    }
}

__global__ void __launch_bounds__(256) convert_wqkv_kernel(
    const float* __restrict__ wq, const float* __restrict__ wk, const float* __restrict__ wv)
{
    int i = blockIdx.x * 256 + threadIdx.x;
    const float* w = (i < 65536) ? wq : (i < 131072) ? wk : wv;
    const float v = w[i & 65535];
    const int proj = i >> 16, r = i & 65535;
    const int o_g = r >> 8, c_g = r & 255;
    const int otile = o_g >> 7, o = o_g & 127, chunk = c_g >> 6, c = c_g & 63;
    const size_t pos = (size_t)(((proj * 2 + otile) * 4 + chunk)) * 8192
                     + (o << 6) + (((c >> 3) ^ (o & 7)) << 3) + (c & 7);
    g_wp2[pos] = __float2half_rn(v);
}

__global__ void __launch_bounds__(256) convert_wconv_kernel(const float* __restrict__ w_out)
{
    int i = blockIdx.x * 256 + threadIdx.x;
    const float v = w_out[i];
    const int o_g = i / 2304;
    const int rem = i - o_g * 2304;
    const int c_g = rem / 9, khw = rem - (rem / 9) * 9;
    const int otile = o_g >> 7, o = o_g & 127, chunk = c_g >> 6, c = c_g & 63;
    const size_t pos = (size_t)(((khw * 2 + otile) * 4 + chunk)) * 8192
                     + (o << 6) + (((c >> 3) ^ (o & 7)) << 3) + (c & 7);
    g_wc2[pos] = __float2half_rn(v);
}

// ---------------- QKV GEMM: bulk pipeline; Q/K fp16, V hi+lo fp16 token-major ----------------
#define QKV_SLOT  32768
#define QKV_SMEM  (1024 + 3*QKV_SLOT)

__global__ void __launch_bounds__(256, 2) qkv_mma_kernel(
    const float* __restrict__ bq, const float* __restrict__ bk, const float* __restrict__ bv)
{
    extern __shared__ char smem[];
    const uint32_t sb = smem_u32(smem);
    const uint32_t data = sb + 1024;
    const int tid = threadIdx.x;
    const int lane = tid & 31, wid = tid >> 5;
    const int wm = wid >> 2, wn = wid & 3;
    const int n0 = blockIdx.x * 128;
    const int otile = blockIdx.y, o0 = otile * 128;
    const int bp = blockIdx.z, proj = bp % 3, b = bp / 3;

    const __half* Asrc = g_wp2 + (size_t)((proj * 2 + otile) * 4) * 8192;
    const __half* Bsrc = g_xt2 + ((size_t)(b * 4) * NPIX + n0) * 64;

    if (tid == 0) { MB_INIT(sb, 1); MB_INIT(sb + 8, 1); MB_INIT(sb + 16, 1); }
    __syncthreads();

    auto issue = [&](int s) {
        const uint32_t mb = sb + (s % 3) * 8;
        const uint32_t dst = data + (s % 3) * QKV_SLOT;
        MB_EXPECT(mb, 32768u);
        bulk_g2s(dst,         Asrc + (size_t)s * 8192,      16384u, mb);
        bulk_g2s(dst + 16384, Bsrc + (size_t)s * NPIX * 64, 16384u, mb);
    };
    if (tid == 0) { issue(0); issue(1); issue(2); }

    float acc[4][4][4];
    #pragma unroll
    for (int i = 0; i < 4; i++)
        #pragma unroll
        for (int j = 0; j < 4; j++)
            #pragma unroll
            for (int q = 0; q < 4; q++) acc[i][j][q] = 0.f;

    #pragma unroll 1
    for (int s = 0; s < 4; s++) {
        MB_WAIT(sb + (s % 3) * 8, (s / 3) & 1);
        const uint32_t ab = data + (s % 3) * QKV_SLOT;
        const uint32_t bb = ab + 16384;
        #pragma unroll
        for (int kh = 0; kh < 4; kh++) {
            uint32_t ah[4][4], bf[4][2];
            #pragma unroll
            for (int i = 0; i < 4; i++) {
                const int row = wm * 64 + i * 16 + (lane & 15);
                const int ch = (2 * kh + (lane >> 4)) ^ (row & 7);
                ldmat4(ah[i], ab + row * 128 + ch * 16);
            }
            #pragma unroll
            for (int jj = 0; jj < 2; jj++) {
                const int row = wn * 32 + jj * 16 + (lane & 7) + ((lane >> 4) << 3);
                const int ch = (2 * kh + ((lane >> 3) & 1)) ^ (row & 7);
                uint32_t r4[4];
                ldmat4(r4, bb + row * 128 + ch * 16);
                bf[2*jj][0] = r4[0]; bf[2*jj][1] = r4[1];
                bf[2*jj+1][0] = r4[2]; bf[2*jj+1][1] = r4[3];
            }
            #pragma unroll
            for (int i = 0; i < 4; i++)
                #pragma unroll
                for (int j = 0; j < 4; j++)
                    mma16816(acc[i][j], ah[i], bf[j]);
        }
        __syncthreads();
        if (tid == 0 && s + 3 < 4) issue(s + 3);
    }

    const float* bias = (proj == 0) ? bq : (proj == 1) ? bk : bv;
    if (proj < 2) {
        __half* qt = ((proj == 0) ? g_qt : g_kt) + (size_t)b * 64 * 16384;
        #pragma unroll
        for (int i = 0; i < 4; i++) {
            const int r0 = o0 + wm * 64 + i * 16 + (lane >> 2);
            const float bb0 = bias[r0], bb1 = bias[r0 + 8];
            #pragma unroll
            for (int j = 0; j < 4; j++) {
                const int p = n0 + wn * 32 + j * 8 + 2 * (lane & 3);
                const int h = p >> 6, w = p & 63;
                const int t = ((h >> 3) << 3) + (w >> 3);
                const int l = ((h & 7) << 3) + (w & 7);
                __half2 v0 = __floats2half2_rn(acc[i][j][0] + bb0, acc[i][j][1] + bb0);
                __half2 v1 = __floats2half2_rn(acc[i][j][2] + bb1, acc[i][j][3] + bb1);
                *(__half2*)(qt + (size_t)t * 16384 + r0 * 64 + l) = v0;
                *(__half2*)(qt + (size_t)t * 16384 + (r0 + 8) * 64 + l) = v1;
            }
        }
    } else {
        __half* vh = g_vt  + (size_t)b * 64 * 16384;
        __half* vl = g_vtl + (size_t)b * 64 * 16384;
        #pragma unroll
        for (int i = 0; i < 4; i++) {
            const int r0 = o0 + wm * 64 + i * 16 + (lane >> 2);
            const float bb0 = bias[r0], bb1 = bias[r0 + 8];
            #pragma unroll
            for (int j = 0; j < 4; j++) {
                const int p = n0 + wn * 32 + j * 8 + 2 * (lane & 3);
                const int h = p >> 6, w = p & 63;
                const int t = ((h >> 3) << 3) + (w >> 3);
                const int l = ((h & 7) << 3) + (w & 7);
                float f0 = acc[i][j][0] + bb0, f1 = acc[i][j][1] + bb0;
                float f2 = acc[i][j][2] + bb1, f3 = acc[i][j][3] + bb1;
                __half h0 = __float2half_rn(f0), h1 = __float2half_rn(f1);
                __half h2 = __float2half_rn(f2), h3 = __float2half_rn(f3);
                __half2 hv0; hv0.x = h0; hv0.y = h1;
                __half2 hv1; hv1.x = h2; hv1.y = h3;
                __half2 lv0 = __floats2half2_rn(f0 - __half2float(h0), f1 - __half2float(h1));
                __half2 lv1 = __floats2half2_rn(f2 - __half2float(h2), f3 - __half2float(h3));
                *(__half2*)(vh + (size_t)t * 16384 + r0 * 64 + l) = hv0;
                *(__half2*)(vh + (size_t)t * 16384 + (r0 + 8) * 64 + l) = hv1;
                *(__half2*)(vl + (size_t)t * 16384 + r0 * 64 + l) = lv0;
                *(__half2*)(vl + (size_t)t * 16384 + (r0 + 8) * 64 + l) = lv1;
            }
        }
    }
}

// ---------------- scores via mma ----------------
#define SC_STAGE 16384
#define SC_SMEM  (3*SC_STAGE)

__global__ void __launch_bounds__(256, 2) scores_mma_kernel()
{
    extern __shared__ char smem[];
    const uint32_t sbase = smem_u32(smem);
    const int tid = threadIdx.x;
    const int lane = tid & 31, wid = tid >> 5;
    const int wm = wid & 3, wn = wid >> 2;
    const int slice = blockIdx.x, b = blockIdx.y;
    const size_t eoff = (size_t)slice * 2048;

    const __half* Q = g_qt + (size_t)b * 64 * 16384 + eoff;
    const __half* K = g_kt + (size_t)b * 64 * 16384 + eoff;

    auto load_stage = [&](int ck, int buf) {
        const uint32_t stb = sbase + buf * SC_STAGE;
        #pragma unroll
        for (int q = 0; q < 2; q++) {
            const int idx = tid + q * 256;
            const int row = idx >> 3, c = idx & 7;
            const uint32_t so = row * 128 + ((c ^ (row & 7)) << 4);
            const size_t goff = (size_t)row * 16384 + ck * 64 + c * 8;
            cp16(stb + so,        Q + goff);
            cp16(stb + 8192 + so, K + goff);
        }
        CP_COMMIT();
    };

    float acc[4][4];
    #pragma unroll
    for (int j = 0; j < 4; j++)
        #pragma unroll
        for (int q = 0; q < 4; q++) acc[j][q] = 0.f;

    load_stage(0, 0);
    load_stage(1, 1);
    #pragma unroll 1
    for (int s = 0; s < 32; s++) {
        if (s + 1 < 32) { CP_WAIT1(); } else { CP_WAIT0(); }
        __syncthreads();
        if (s + 2 < 32) load_stage(s + 2, (s + 2) % 3);
        const uint32_t qb = sbase + (s % 3) * SC_STAGE;
        const uint32_t kb = qb + 8192;
        #pragma unroll
        for (int kh = 0; kh < 4; kh++) {
            uint32_t ah[4], bf[4][2];
            {
                const int row = wm * 16 + (lane & 15);
                const int ch = (2 * kh + (lane >> 4)) ^ (row & 7);
                ldmat4(ah, qb + row * 128 + ch * 16);
            }
            #pragma unroll
            for (int jj = 0; jj < 2; jj++) {
                const int row = wn * 32 + jj * 16 + (lane & 7) + ((lane >> 4) << 3);
                const int ch = (2 * kh + ((lane >> 3) & 1)) ^ (row & 7);
                uint32_t r4[4];
                ldmat4(r4, kb + row * 128 + ch * 16);
                bf[2*jj][0] = r4[0]; bf[2*jj][1] = r4[1];
                bf[2*jj+1][0] = r4[2]; bf[2*jj+1][1] = r4[3];
            }
            #pragma unroll
            for (int j = 0; j < 4; j++)
                mma16816(acc[j], ah, bf[j]);
        }
        __syncthreads();
    }

    float* dst = g_spart + ((size_t)(b * 8 + slice)) * 4096;
    #pragma unroll
    for (int j = 0; j < 4; j++) {
        const int r0 = wm * 16 + (lane >> 2);
        const int cb = wn * 32 + j * 8 + 2 * (lane & 3);
        *(float2*)(dst + r0 * 64 + cb)       = make_float2(acc[j][0], acc[j][1]);
        *(float2*)(dst + (r0 + 8) * 64 + cb) = make_float2(acc[j][2], acc[j][3]);
    }
}

// ---------------- softmax -> attn hi/lo fp16 ----------------
__global__ void __launch_bounds__(64) softmax_kernel()
{
    const int b = blockIdx.x;
    const int t = threadIdx.x;
    const float scale = 1.0f / 128.0f;
    float v[64];
    #pragma unroll
    for (int u = 0; u < 64; u++) v[u] = 0.f;
    #pragma unroll 2
    for (int sl = 0; sl < 8; sl++) {
        const float* row = g_spart + ((size_t)(b * 8 + sl)) * 4096 + t * 64;
        #pragma unroll
        for (int u = 0; u < 64; u++) v[u] += row[u];
    }
    float m = -1e30f;
    #pragma unroll
    for (int u = 0; u < 64; u++) { v[u] *= scale; m = fmaxf(m, v[u]); }
    float s = 0.f;
    #pragma unroll
    for (int u = 0; u < 64; u++) { v[u] = __expf(v[u] - m); s += v[u]; }
    const float inv = 1.0f / s;
    __half* hrow = g_attn_h + b * 4096 + t * 64;
    __half* lrow = g_attn_l + b * 4096 + t * 64;
    #pragma unroll
    for (int u = 0; u < 64; u += 2) {
        float f0 = v[u] * inv, f1 = v[u+1] * inv;
        __half h0 = __float2half_rn(f0), h1 = __float2half_rn(f1);
        __half2 hh; hh.x = h0; hh.y = h1;
        *(__half2*)(hrow + u) = hh;
        *(__half2*)(lrow + u) = __floats2half2_rn(f0 - __half2float(h0), f1 - __half2float(h1));
    }
}

// ---------------- av via mma (4-term hi/lo): Out = attn @ Vt; scatter to conv layout ----------------
#define AV_AL   8192
#define AV_VH   16384
#define AV_VL   49152
#define AV_OUT  81920
#define AV_SMEM 114688

__global__ void __launch_bounds__(256, 2) av_mma_kernel()
{
    extern __shared__ char smem[];
    const uint32_t sbase = smem_u32(smem);
    const int tid = threadIdx.x;
    const int lane = tid & 31, wid = tid >> 5;
    const int wm = wid >> 1, wn = wid & 1;      // warp tile: 16 t x 128 e
    const int et = blockIdx.x, b = blockIdx.y;
    const size_t e0 = (size_t)et * 256;

    {
        const __half* Ah = g_attn_h + (size_t)b * 4096;
        const __half* Al = g_attn_l + (size_t)b * 4096;
        const __half* Vh = g_vt  + (size_t)b * 64 * 16384 + e0;
        const __half* Vl = g_vtl + (size_t)b * 64 * 16384 + e0;
        #pragma unroll
        for (int q = 0; q < 2; q++) {
            const int idx = tid + q * 256;
            const int row = idx >> 3, c = idx & 7;
            const uint32_t so = row * 128 + ((c ^ (row & 7)) << 4);
            cp16(sbase + so,         Ah + (size_t)row * 64 + c * 8);
            cp16(sbase + AV_AL + so, Al + (size_t)row * 64 + c * 8);
        }
        #pragma unroll
        for (int q = 0; q < 8; q++) {
            const int idx = tid + q * 256;
            const int row = idx >> 5, c = idx & 31;
            const int sw = (c & 24) | ((c & 7) ^ (row & 7));
            cp16(sbase + AV_VH + row * 512 + sw * 16, Vh + (size_t)row * 16384 + c * 8);
            cp16(sbase + AV_VL + row * 512 + sw * 16, Vl + (size_t)row * 16384 + c * 8);
        }
        CP_COMMIT();
        CP_WAIT0();
    }
    __syncthreads();

    float acc[16][4];
    #pragma unroll
    for (int j = 0; j < 16; j++)
        #pragma unroll
        for (int q = 0; q < 4; q++) acc[j][q] = 0.f;

    #pragma unroll
    for (int kh = 0; kh < 4; kh++) {
        uint32_t ahh[4], ahl[4];
        {
            const int row = wm * 16 + (lane & 15);
            const int ch = (2 * kh + (lane >> 4)) ^ (row & 7);
            ldmat4(ahh, sbase + row * 128 + ch * 16);
            ldmat4(ahl, sbase + AV_AL + row * 128 + ch * 16);
        }
        #pragma unroll
        for (int jj = 0; jj < 8; jj++) {
            const int u = kh * 16 + (lane & 15);
            const int c32 = wn * 16 + jj * 2 + (lane >> 4);
            const int sw = (c32 & 24) | ((c32 & 7) ^ (u & 7));
            uint32_t rh[4], rl[4];
            ldmat4t(rh, sbase + AV_VH + u * 512 + sw * 16);
            ldmat4t(rl, sbase + AV_VL + u * 512 + sw * 16);
            uint32_t bh0[2] = { rh[0], rh[1] }, bh1[2] = { rh[2], rh[3] };
            uint32_t bl0[2] = { rl[0], rl[1] }, bl1[2] = { rl[2], rl[3] };
            mma16816(acc[jj*2],   ahh, bh0);
            mma16816(acc[jj*2],   ahh, bl0);
            mma16816(acc[jj*2],   ahl, bh0);
            mma16816(acc[jj*2],   ahl, bl0);
            mma16816(acc[jj*2+1], ahh, bh1);
            mma16816(acc[jj*2+1], ahh, bl1);
            mma16816(acc[jj*2+1], ahl, bh1);
            mma16816(acc[jj*2+1], ahl, bl1);
        }
    }

    #pragma unroll
    for (int j = 0; j < 16; j++) {
        const int t0 = wm * 16 + (lane >> 2);
        const int e  = wn * 128 + j * 8 + 2 * (lane & 3);
        const int c  = e >> 3;
        const int sw0 = (c & 24) | ((c & 7) ^ (t0 & 7));
        const int sw1 = (c & 24) | ((c & 7) ^ ((t0 + 8) & 7));
        __half2 v0 = __floats2half2_rn(acc[j][0], acc[j][1]);
        __half2 v1 = __floats2half2_rn(acc[j][2], acc[j][3]);
        *(__half2*)(smem + AV_OUT + t0 * 512 + sw0 * 16 + (e & 7) * 2) = v0;
        *(__half2*)(smem + AV_OUT + (t0 + 8) * 512 + sw1 * 16 + (e & 7) * 2) = v1;
    }
    __syncthreads();

    const int d0g = et * 4;
    const int chunk_g = d0g >> 6, cl0 = d0g & 63;
    __half* outg = g_aot2 + ((size_t)(b * 4 + chunk_g)) * NPIX * 64;
    #pragma unroll
    for (int p = 0; p < 16; p++) {
        const int pix = tid + p * 256;
        const int h = pix >> 6, w = pix & 63;
        const int t = ((h >> 3) << 3) + (w >> 3);
        const int l = ((h & 7) << 3) + (w & 7);
        uint32_t hv[4];
        #pragma unroll
        for (int dq = 0; dq < 4; dq++) {
            const int sw = dq * 8 + ((l >> 3) ^ (t & 7));
            hv[dq] = *(const uint16_t*)(smem + AV_OUT + t * 512 + sw * 16 + (l & 7) * 2);
        }
        uint2 pk;
        pk.x = hv[0] | (hv[1] << 16);
        pk.y = hv[2] | (hv[3] << 16);
        const size_t off = (size_t)pix * 64 + (((cl0 >> 3) ^ (pix & 7)) << 3) + (cl0 & 7);
        *(uint2*)(outg + off) = pk;
    }
}

// ---------------- conv 3x3: 4 warps, 64x64 warp tile, bulk pipeline + BN + LeakyReLU ----------------
#define CV_A_SLOT  16384
#define CV_HALO    (1024 + 3*CV_A_SLOT)
#define CV_SMEM    (CV_HALO + 33792)

__global__ void __launch_bounds__(128, 2) conv_mma_kernel(
    const float* __restrict__ b_out, const float* __restrict__ gamma,
    const float* __restrict__ beta,  const float* __restrict__ bn_mean,
    const float* __restrict__ bn_var, float* __restrict__ out)
{
    extern __shared__ char smem[];
    const uint32_t sb = smem_u32(smem);
    const uint32_t data = sb + 1024;
    const uint32_t halo = sb + CV_HALO;
    const int tid = threadIdx.x;
    const int lane = tid & 31, wid = tid >> 5;       // 4 warps
    const int wm = wid >> 1, wn = wid & 1;           // warp tile: o64 x pix64
    const int pt = blockIdx.x;
    const int otile = blockIdx.y, o0 = otile * 128;
    const int b = blockIdx.z;
    const int h0 = pt * 2, n0 = pt * 128;

    const __half* Bbase = g_aot2 + (size_t)(b * 4) * NPIX * 64;

    if (tid == 0) { MB_INIT(sb, 1); MB_INIT(sb + 8, 1); MB_INIT(sb + 16, 1); MB_INIT(sb + 24, 1); }
    {
        const int4 z = make_int4(0, 0, 0, 0);
        for (int idx = tid; idx < 2112; idx += 128)
            *(int4*)(smem + CV_HALO + idx * 16) = z;
    }
    __syncthreads();

    auto issueA = [&](int s) {
        const int khw = s % 9, chunk = s / 9;
        const uint32_t mb = sb + (s % 3) * 8;
        MB_EXPECT(mb, 16384u);
        bulk_g2s(data + (s % 3) * CV_A_SLOT,
                 g_wc2 + (size_t)((khw * 2 + otile) * 4 + chunk) * 8192, 16384u, mb);
    };
    auto issueHalo = [&](int chunk) {
        const uint32_t mb = sb + 24;
        uint32_t bytes = 0;
        #pragma unroll
        for (int hr = 0; hr < 4; hr++) {
            const int h2 = h0 - 1 + hr;
            if ((unsigned)h2 < 64u) bytes += 8192u;
        }
        MB_EXPECT(mb, bytes);
        #pragma unroll
        for (int hr = 0; hr < 4; hr++) {
            const int h2 = h0 - 1 + hr;
            if ((unsigned)h2 < 64u)
                bulk_g2s(halo + hr * 8448 + 128,
                         Bbase + ((size_t)chunk * NPIX + h2 * 64) * 64, 8192u, mb);
        }
    };
    if (tid == 0) { issueHalo(0); issueA(0); issueA(1); issueA(2); }

    float acc[4][8][4];
    #pragma unroll
    for (int i = 0; i < 4; i++)
        #pragma unroll
        for (int j = 0; j < 8; j++)
            #pragma unroll
            for (int q = 0; q < 4; q++) acc[i][j][q] = 0.f;

    #pragma unroll 1
    for (int s = 0; s < 36; s++) {
        const int khw = s % 9, chunk = s / 9;
        MB_WAIT(sb + (s % 3) * 8, (s / 3) & 1);
        if (khw == 0) MB_WAIT(sb + 24, chunk & 1);
        const int dh = khw / 3 - 1, dw = khw % 3 - 1;
        const uint32_t ab = data + (s % 3) * CV_A_SLOT;
        #pragma unroll
        for (int kh = 0; kh < 4; kh++) {
            uint32_t ah[4][4], bf[8][2];
            #pragma unroll
            for (int i = 0; i < 4; i++) {
                const int row = wm * 64 + i * 16 + (lane & 15);
                const int ch = (2 * kh + (lane >> 4)) ^ (row & 7);
                ldmat4(ah[i], ab + row * 128 + ch * 16);
            }
            #pragma unroll
            for (int jj = 0; jj < 4; jj++) {
                const int p = wn * 64 + jj * 16 + (lane & 7) + ((lane >> 4) << 3);
                const int w2 = (p & 63) + dw;
                const int er = (p >> 6) + dh + 1;
                const int e = er * 66 + w2 + 1;
                const int ch = (2 * kh + ((lane >> 3) & 1)) ^ (w2 & 7);
                uint32_t r4[4];
                ldmat4(r4, halo + e * 128 + ch * 16);
                bf[2*jj][0] = r4[0]; bf[2*jj][1] = r4[1];
                bf[2*jj+1][0] = r4[2]; bf[2*jj+1][1] = r4[3];
            }
            #pragma unroll
            for (int i = 0; i < 4; i++)
                #pragma unroll
                for (int j = 0; j < 8; j++)
                    mma16816(acc[i][j], ah[i], bf[j]);
        }
        __syncthreads();
        if (tid == 0) {
            if (s + 3 < 36) issueA(s + 3);
            if (khw == 8 && chunk < 3) issueHalo(chunk + 1);
        }
    }

    float* dst = out + (size_t)b * ND * NPIX;
    #pragma unroll
    for (int i = 0; i < 4; i++) {
        const int r0 = o0 + wm * 64 + i * 16 + (lane >> 2);
        const float sc0 = gamma[r0]     * rsqrtf(bn_var[r0]     + 1e-5f);
        const float sc1 = gamma[r0 + 8] * rsqrtf(bn_var[r0 + 8] + 1e-5f);
        const float ad0 = (b_out[r0]     - bn_mean[r0])     * sc0 + beta[r0];
        const float ad1 = (b_out[r0 + 8] - bn_mean[r0 + 8]) * sc1 + beta[r0 + 8];
        #pragma unroll
        for (int j = 0; j < 8; j++) {
            const int cb = n0 + wn * 64 + j * 8 + 2 * (lane & 3);
            float t0 = acc[i][j][0] * sc0 + ad0;
            float t1 = acc[i][j][1] * sc0 + ad0;
            float t2 = acc[i][j][2] * sc1 + ad1;
            float t3 = acc[i][j][3] * sc1 + ad1;
            float2 v0 = make_float2((t0 >= 0.f) ? t0 : 0.2f * t0,
                                    (t1 >= 0.f) ? t1 : 0.2f * t1);
            float2 v1 = make_float2((t2 >= 0.f) ? t2 : 0.2f * t2,
                                    (t3 >= 0.f) ? t3 : 0.2f * t3);
            *(float2*)(dst + (size_t)r0 * NPIX + cb) = v0;
            *(float2*)(dst + (size_t)(r0 + 8) * NPIX + cb) = v1;
        }
    }
}

// ---------------- host ----------------
extern "C" void kernel_launch(void* const* d_in, const int* in_sizes, int n_in,
                              void* d_out, int out_size)
{
    const float* x       = (const float*)d_in[0];
    const float* wq      = (const float*)d_in[1];
    const float* bq      = (const float*)d_in[2];
    const float* wk      = (const float*)d_in[3];
    const float* bk      = (const float*)d_in[4];
    const float* wv      = (const float*)d_in[5];
    const float* bv      = (const float*)d_in[6];
    const float* w_out   = (const float*)d_in[7];
    const float* b_out   = (const float*)d_in[8];
    const float* gamma   = (const float*)d_in[9];
    const float* beta    = (const float*)d_in[10];
    const float* bn_mean = (const float*)d_in[11];
    const float* bn_var  = (const float*)d_in[12];
    float* out = (float*)d_out;

    cudaFuncSetAttribute(qkv_mma_kernel,    cudaFuncAttributeMaxDynamicSharedMemorySize, QKV_SMEM);
    cudaFuncSetAttribute(scores_mma_kernel, cudaFuncAttributeMaxDynamicSharedMemorySize, SC_SMEM);
    cudaFuncSetAttribute(av_mma_kernel,     cudaFuncAttributeMaxDynamicSharedMemorySize, AV_SMEM);
    cudaFuncSetAttribute(conv_mma_kernel,   cudaFuncAttributeMaxDynamicSharedMemorySize, CV_SMEM);

    convert_wqkv_kernel <<<768,  256>>>(wq, wk, wv);
    convert_wconv_kernel<<<2304, 256>>>(w_out);
    convert_x_kernel<<<dim3(128, 8, 16), 256>>>(x);

    qkv_mma_kernel<<<dim3(32, 2, 48), 256, QKV_SMEM>>>(bq, bk, bv);

    scores_mma_kernel<<<dim3(8, 16), 256, SC_SMEM>>>();
    softmax_kernel<<<16, 64>>>();
    av_mma_kernel<<<dim3(64, 16), 256, AV_SMEM>>>();

    conv_mma_kernel<<<dim3(32, 2, 16), 128, CV_SMEM>>>(b_out, gamma, beta, bn_mean, bn_var, out);
}